// round 3
// baseline (speedup 1.0000x reference)
#include <cuda_runtime.h>
#include <cstdint>

#define B_ 64
#define T_ 128
#define F_ 1024
#define S_ 512
#define M_ 2048
#define EPS_ 0.45f

// ---------------- device scratch (static, no allocation) ----------------
__device__ float g_mem[M_ * F_];            // carry: memory (8 MB)
__device__ float g_idx[M_];                 // carry: index
__device__ float g_updq[F_];                // upd_mem_q vector for current step
__device__ float g_upds[B_ * F_];           // precomputed upd_mem_s per step
__device__ float g_updidxs[B_];             // precomputed upd_idx_s per step
__device__ unsigned long long g_packed[B_]; // per-step cq argmax (value<<32 | ~m)
__device__ int g_flagq[B_];                 // per-step cond_q
__device__ int g_flags[B_];                 // per-step cond_s
__device__ unsigned char g_action[M_];      // per-row action for current step
__device__ int g_li;                        // leader index for current step

// ---------------- helpers ----------------
// comp = 0.5 - clip(0.2*(x - s) + 0.5, 0, 1), no FMA contraction (exact op order)
__device__ __forceinline__ float comp_fn(float x, float s) {
    float d  = __fsub_rn(x, s);
    float t  = __fadd_rn(__fmul_rn(0.2f, d), 0.5f);
    float hs = fminf(fmaxf(t, 0.0f), 1.0f);
    return __fsub_rn(0.5f, hs);
}

// order-preserving float <-> uint (for atomicMax argmax). Normalize -0 -> +0 before encode.
__device__ __forceinline__ unsigned fenc(float x) {
    unsigned u = __float_as_uint(x);
    return (u & 0x80000000u) ? ~u : (u | 0x80000000u);
}
__device__ __forceinline__ float fdec(unsigned u) {
    unsigned v = (u & 0x80000000u) ? (u & 0x7FFFFFFFu) : ~u;
    return __uint_as_float(v);
}
__device__ __forceinline__ unsigned long long pack_vm(float v, int m) {
    return ((unsigned long long)fenc(__fadd_rn(v, 0.0f)) << 32) |
           (unsigned long long)(0xFFFFFFFFu - (unsigned)m);
}

// ---------------- kernels ----------------
// init: zero per-step atomic slots, copy index -> g_idx
__global__ void k_init(const float* __restrict__ index) {
    int i = blockIdx.x * blockDim.x + threadIdx.x;  // 8*256 = 2048 threads
    if (i < B_) { g_packed[i] = 0ull; g_flagq[i] = 0; g_flags[i] = 0; }
    if (i < M_) g_idx[i] = index[i];
}

// precompute (parallel over all steps): cond_s, upd_mem_s, upd_idx_s
// grid: (32, 64) blocks, 256 threads. block (j,b): columns j*32..j*32+31, all S rows.
__global__ void k_pre(const float* __restrict__ states, const float* __restrict__ mr) {
    const int j = blockIdx.x, b = blockIdx.y;
    const int tx = threadIdx.x & 31, ty = threadIdx.x >> 5;   // 32 cols x 8 row-groups
    const int f = j * 32 + tx;
    const float* s   = states + ((size_t)b * T_ + (T_ - 1)) * F_;
    const float  sf  = s[f];
    const float* mrb = mr + (size_t)b * S_ * F_;

    float mx = -3.402823466e38f;  // column max of mr
    float ma = 0.0f;              // column max of |comp|
    int any = 0;
    for (int ri = ty; ri < S_; ri += 8) {
        float v  = mrb[(size_t)ri * F_ + f];
        float cp = comp_fn(v, sf);
        any |= (cp >= EPS_);
        ma = fmaxf(ma, fabsf(cp));
        mx = fmaxf(mx, v);
    }
    __shared__ float smx[256], sma[256];
    __shared__ int   sany[8];
    smx[threadIdx.x] = mx; sma[threadIdx.x] = ma;
    unsigned bal = __ballot_sync(0xffffffffu, any);
    if (tx == 0) sany[ty] = (bal != 0u);
    __syncthreads();
    if (ty == 0) {
        float amx = smx[tx], ama = sma[tx];
        #pragma unroll
        for (int g = 1; g < 8; g++) {
            amx = fmaxf(amx, smx[g * 32 + tx]);
            ama = fmaxf(ama, sma[g * 32 + tx]);
        }
        const float SQRT_S = sqrtf((float)S_);                 // fl(sqrt(512))
        float cs = __fmul_rn(SQRT_S, ama);                     // comp_s[f]
        // upd_mem_s[f] = max_i(mr*cs + s*(1-cs)) == value at column max (cs>=0, monotone)
        g_upds[(size_t)b * F_ + f] =
            __fadd_rn(__fmul_rn(amx, cs), __fmul_rn(sf, __fsub_rn(1.0f, cs)));
        if (f == F_ - 1) {
            float mr0 = mrb[F_ - 1];   // mr[0, -1]
            float r   = sf;            // s[-1]
            g_updidxs[b] = __fadd_rn(__fmul_rn(mr0, cs),
                                     __fmul_rn(r, __fsub_rn(1.0f, cs)));
        }
        if (tx == 0) {
            int a = 0;
            #pragma unroll
            for (int g = 0; g < 8; g++) a |= sany[g];
            if (a) atomicOr(&g_flags[b], 1);
        }
    }
}

// copy input memory -> g_mem, fused with step-0 cond_q / cq scan. grid: 2048 blocks (one per row)
__global__ void k_copyscan(const float* __restrict__ memin, const float* __restrict__ states) {
    const int m = blockIdx.x;
    const float* s0  = states + (size_t)(T_ - 1) * F_;
    const float* src = memin + (size_t)m * F_;
    float* dst = g_mem + (size_t)m * F_;
    int any = 0;
    for (int f = threadIdx.x; f < F_; f += 256) {
        float v = src[f];
        dst[f] = v;
        float cp = comp_fn(v, s0[f]);
        any |= (cp >= EPS_);
        if (f == F_ - 1) atomicMax(&g_packed[0], pack_vm(cp, m));
    }
    any = __syncthreads_or(any);
    if (threadIdx.x == 0 && any) atomicOr(&g_flagq[0], 1);
}

// per-step scalar/idx chain. one block, 256 threads (8 rows per thread).
__global__ void k_idx(int b, const float* __restrict__ states, float* __restrict__ out) {
    __shared__ float sred[256];
    __shared__ unsigned long long spk[256];
    const int tid = threadIdx.x;
    const float* s = states + ((size_t)b * T_ + (T_ - 1)) * F_;
    const float r = s[F_ - 1];
    const int condq = g_flagq[b];
    const int conds = g_flags[b];
    unsigned long long pk = g_packed[b];
    const float c  = fdec((unsigned)(pk >> 32));
    const int   mi = (int)(0xFFFFFFFFu - (unsigned)(pk & 0xFFFFFFFFull));
    const float one_m_c = __fsub_rn(1.0f, c);
    const float idxmi = g_idx[mi];
    const float updq_i = __fadd_rn(__fmul_rn(idxmi, one_m_c), __fmul_rn(r, c));
    const float updidxs = g_updidxs[b];

    float i1[8]; unsigned char mq[8];
    #pragma unroll
    for (int k = 0; k < 8; k++) {
        int m = k * 256 + tid;
        float iv  = g_idx[m];
        float cqm = comp_fn(g_mem[(size_t)m * F_ + (F_ - 1)], s[F_ - 1]);
        bool maskq = (cqm == c);
        mq[k] = maskq;
        i1[k] = condq ? (maskq ? iv : updq_i) : iv;
    }
    // t1 = max(-idx1)
    float lm = -i1[0];
    #pragma unroll
    for (int k = 1; k < 8; k++) lm = fmaxf(lm, -i1[k]);
    sred[tid] = lm; __syncthreads();
    for (int st = 128; st > 0; st >>= 1) {
        if (tid < st) sred[tid] = fmaxf(sred[tid], sred[tid + st]);
        __syncthreads();
    }
    const float t1 = sred[0]; __syncthreads();

    float i2[8]; unsigned char mm1[8];
    #pragma unroll
    for (int k = 0; k < 8; k++) {
        bool mk = (i1[k] == t1);
        mm1[k] = mk;
        i2[k] = conds ? (mk ? updidxs : i1[k]) : i1[k];
    }
    lm = -i2[0];
    #pragma unroll
    for (int k = 1; k < 8; k++) lm = fmaxf(lm, -i2[k]);
    sred[tid] = lm; __syncthreads();
    for (int st = 128; st > 0; st >>= 1) {
        if (tid < st) sred[tid] = fmaxf(sred[tid], sred[tid + st]);
        __syncthreads();
    }
    const float t2 = sred[0]; __syncthreads();

    const int conde = (!condq) && (!conds);
    unsigned long long best = 0ull;
    #pragma unroll
    for (int k = 0; k < 8; k++) {
        int m = k * 256 + tid;
        bool m2 = (i2[k] == t2);
        float i3 = conde ? (m2 ? r : i2[k]) : i2[k];
        g_idx[m] = i3;
        unsigned char act = 0;
        if (conde && m2)            act = 3;
        else if (conds && mm1[k])   act = 2;
        else if (condq && !mq[k])   act = 1;
        g_action[m] = act;
        unsigned long long p = pack_vm(i3, m);
        if (p > best) best = p;
    }
    spk[tid] = best; __syncthreads();
    for (int st = 128; st > 0; st >>= 1) {
        if (tid < st) spk[tid] = max(spk[tid], spk[tid + st]);
        __syncthreads();
    }
    if (tid == 0) {
        int li = (int)(0xFFFFFFFFu - (unsigned)(spk[0] & 0xFFFFFFFFull));
        g_li = li;
        out[(size_t)B_ * F_ + b] = g_idx[li];   // importances[b]
    }
    __syncthreads();
    // materialize upd_mem_q = memory[mi]*(1-c) + s*c (before any row gets overwritten)
    const float* memrow = g_mem + (size_t)mi * F_;
    for (int f = tid; f < F_; f += 256)
        g_updq[f] = __fadd_rn(__fmul_rn(memrow[f], one_m_c), __fmul_rn(s[f], c));
}

// apply actions, emit targets[b], fused scan for step b+1. grid: 2048 blocks (one per row)
__global__ void k_apply(int b, int do_next,
                        const float* __restrict__ states, float* __restrict__ out) {
    const int m = blockIdx.x;
    const int act = g_action[m];
    const int li = g_li;
    const bool isLi = (m == li);
    if (act == 0 && !do_next && !isLi) return;

    float* row = g_mem + (size_t)m * F_;
    const float* upds  = g_upds + (size_t)b * F_;
    const float* s     = states + ((size_t)b * T_ + (T_ - 1)) * F_;
    const float* snext = states + ((size_t)(b + 1) * T_ + (T_ - 1)) * F_;
    int any = 0;
    for (int f = threadIdx.x; f < F_; f += 256) {
        float v;
        if (act == 0)      v = row[f];
        else if (act == 1) v = g_updq[f];
        else if (act == 2) v = upds[f];
        else               v = s[f];
        if (act) row[f] = v;
        if (isLi) out[(size_t)b * F_ + f] = v;   // targets[b]
        if (do_next) {
            float cp = comp_fn(v, snext[f]);
            any |= (cp >= EPS_);
            if (f == F_ - 1) atomicMax(&g_packed[b + 1], pack_vm(cp, m));
        }
    }
    if (do_next) {
        any = __syncthreads_or(any);
        if (threadIdx.x == 0 && any) atomicOr(&g_flagq[b + 1], 1);
    }
}

// ---------------- launch ----------------
extern "C" void kernel_launch(void* const* d_in, const int* in_sizes, int n_in,
                              void* d_out, int out_size) {
    const float* states = (const float*)d_in[0];   // (64,128,1024)
    const float* mr     = (const float*)d_in[1];   // (64,512,1024)
    const float* memin  = (const float*)d_in[2];   // (2048,1024)
    const float* index  = (const float*)d_in[3];   // (2048,1)
    float* out = (float*)d_out;                    // targets(64*1024) ++ importances(64)

    k_init<<<8, 256>>>(index);
    k_pre<<<dim3(32, B_), 256>>>(states, mr);
    k_copyscan<<<M_, 256>>>(memin, states);
    for (int b = 0; b < B_; b++) {
        k_idx<<<1, 256>>>(b, states, out);
        k_apply<<<M_, 256>>>(b, (b < B_ - 1) ? 1 : 0, states, out);
    }
}

// round 4
// speedup vs baseline: 1.0060x; 1.0060x over previous
#include <cuda_runtime.h>
#include <cstdint>

#define B_ 64
#define T_ 128
#define F_ 1024
#define S_ 512
#define M_ 2048
#define EPS_ 0.45f

// ---------------- device scratch (static, no allocation) ----------------
__device__ float g_mem[M_ * F_];            // carry: memory (8 MB)
__device__ float g_idx[M_];                 // carry: index
__device__ float g_updq[F_];                // upd_mem_q vector for current step
__device__ float g_upds[B_ * F_];           // precomputed upd_mem_s per step
__device__ float g_updidxs[B_];             // precomputed upd_idx_s per step
__device__ unsigned long long g_packed[B_]; // per-step cq argmax (value<<32 | ~m)
__device__ int g_flagq[B_];                 // per-step cond_q
__device__ int g_flags[B_];                 // per-step cond_s
__device__ unsigned char g_action[M_];      // per-row action for current step
__device__ int g_li;                        // leader index for current step

// ---------------- helpers ----------------
// comp = 0.5 - clip(0.2*(x - s) + 0.5, 0, 1), no FMA contraction (exact op order)
__device__ __forceinline__ float comp_fn(float x, float s) {
    float d  = __fsub_rn(x, s);
    float t  = __fadd_rn(__fmul_rn(0.2f, d), 0.5f);
    float hs = fminf(fmaxf(t, 0.0f), 1.0f);
    return __fsub_rn(0.5f, hs);
}

// order-preserving float <-> uint (for atomicMax argmax). Normalize -0 -> +0 before encode.
__device__ __forceinline__ unsigned fenc(float x) {
    unsigned u = __float_as_uint(x);
    return (u & 0x80000000u) ? ~u : (u | 0x80000000u);
}
__device__ __forceinline__ float fdec(unsigned u) {
    unsigned v = (u & 0x80000000u) ? (u & 0x7FFFFFFFu) : ~u;
    return __uint_as_float(v);
}
__device__ __forceinline__ unsigned long long pack_vm(float v, int m) {
    return ((unsigned long long)fenc(__fadd_rn(v, 0.0f)) << 32) |
           (unsigned long long)(0xFFFFFFFFu - (unsigned)m);
}

// ---------------- kernels ----------------
// init: zero per-step atomic slots, copy index -> g_idx
__global__ void k_init(const float* __restrict__ index) {
    int i = blockIdx.x * blockDim.x + threadIdx.x;  // 8*256 = 2048 threads
    if (i < B_) { g_packed[i] = 0ull; g_flagq[i] = 0; g_flags[i] = 0; }
    if (i < M_) g_idx[i] = index[i];
}

// precompute (parallel over all steps): cond_s, upd_mem_s, upd_idx_s
// grid: (32, 64) blocks, 256 threads. block (j,b): columns j*32..j*32+31, all S rows.
__global__ void k_pre(const float* __restrict__ states, const float* __restrict__ mr) {
    const int j = blockIdx.x, b = blockIdx.y;
    const int tx = threadIdx.x & 31, ty = threadIdx.x >> 5;   // 32 cols x 8 row-groups
    const int f = j * 32 + tx;
    const float* s   = states + ((size_t)b * T_ + (T_ - 1)) * F_;
    const float  sf  = s[f];
    const float* mrb = mr + (size_t)b * S_ * F_;

    float mx = -3.402823466e38f;  // column max of mr
    float ma = 0.0f;              // column max of |comp|
    int any = 0;
    for (int ri = ty; ri < S_; ri += 8) {
        float v  = mrb[(size_t)ri * F_ + f];
        float cp = comp_fn(v, sf);
        any |= (cp >= EPS_);
        ma = fmaxf(ma, fabsf(cp));
        mx = fmaxf(mx, v);
    }
    __shared__ float smx[256], sma[256];
    __shared__ int   sany[8];
    smx[threadIdx.x] = mx; sma[threadIdx.x] = ma;
    unsigned bal = __ballot_sync(0xffffffffu, any);
    if (tx == 0) sany[ty] = (bal != 0u);
    __syncthreads();
    if (ty == 0) {
        float amx = smx[tx], ama = sma[tx];
        #pragma unroll
        for (int g = 1; g < 8; g++) {
            amx = fmaxf(amx, smx[g * 32 + tx]);
            ama = fmaxf(ama, sma[g * 32 + tx]);
        }
        const float SQRT_S = sqrtf((float)S_);                 // fl(sqrt(512))
        float cs = __fmul_rn(SQRT_S, ama);                     // comp_s[f]
        // upd_mem_s[f] = max_i(mr*cs + s*(1-cs)) == value at column max (cs>=0, monotone)
        g_upds[(size_t)b * F_ + f] =
            __fadd_rn(__fmul_rn(amx, cs), __fmul_rn(sf, __fsub_rn(1.0f, cs)));
        if (f == F_ - 1) {
            float mr0 = mrb[F_ - 1];   // mr[0, -1]
            float r   = sf;            // s[-1]
            g_updidxs[b] = __fadd_rn(__fmul_rn(mr0, cs),
                                     __fmul_rn(r, __fsub_rn(1.0f, cs)));
        }
        if (tx == 0) {
            int a = 0;
            #pragma unroll
            for (int g = 0; g < 8; g++) a |= sany[g];
            if (a) atomicOr(&g_flags[b], 1);
        }
    }
}

// copy input memory -> g_mem, fused with step-0 cond_q / cq scan. grid: 2048 blocks (one per row)
__global__ void k_copyscan(const float* __restrict__ memin, const float* __restrict__ states) {
    const int m = blockIdx.x;
    const float* s0  = states + (size_t)(T_ - 1) * F_;
    const float* src = memin + (size_t)m * F_;
    float* dst = g_mem + (size_t)m * F_;
    int any = 0;
    for (int f = threadIdx.x; f < F_; f += 256) {
        float v = src[f];
        dst[f] = v;
        float cp = comp_fn(v, s0[f]);
        any |= (cp >= EPS_);
        if (f == F_ - 1) atomicMax(&g_packed[0], pack_vm(cp, m));
    }
    any = __syncthreads_or(any);
    if (threadIdx.x == 0 && any) atomicOr(&g_flagq[0], 1);
}

// per-step scalar/idx chain. one block, 256 threads (8 rows per thread).
__global__ void k_idx(int b, const float* __restrict__ states, float* __restrict__ out) {
    __shared__ float sred[256];
    __shared__ unsigned long long spk[256];
    const int tid = threadIdx.x;
    const float* s = states + ((size_t)b * T_ + (T_ - 1)) * F_;
    const float r = s[F_ - 1];
    const int condq = g_flagq[b];
    const int conds = g_flags[b];
    unsigned long long pk = g_packed[b];
    const float c  = fdec((unsigned)(pk >> 32));
    const int   mi = (int)(0xFFFFFFFFu - (unsigned)(pk & 0xFFFFFFFFull));
    const float one_m_c = __fsub_rn(1.0f, c);
    const float idxmi = g_idx[mi];
    const float updq_i = __fadd_rn(__fmul_rn(idxmi, one_m_c), __fmul_rn(r, c));
    const float updidxs = g_updidxs[b];

    float i1[8]; unsigned char mq[8];
    #pragma unroll
    for (int k = 0; k < 8; k++) {
        int m = k * 256 + tid;
        float iv  = g_idx[m];
        float cqm = comp_fn(g_mem[(size_t)m * F_ + (F_ - 1)], s[F_ - 1]);
        bool maskq = (cqm == c);
        mq[k] = maskq;
        i1[k] = condq ? (maskq ? iv : updq_i) : iv;
    }
    // t1 = max(-idx1)
    float lm = -i1[0];
    #pragma unroll
    for (int k = 1; k < 8; k++) lm = fmaxf(lm, -i1[k]);
    sred[tid] = lm; __syncthreads();
    for (int st = 128; st > 0; st >>= 1) {
        if (tid < st) sred[tid] = fmaxf(sred[tid], sred[tid + st]);
        __syncthreads();
    }
    const float t1 = sred[0]; __syncthreads();

    float i2[8]; unsigned char mm1[8];
    #pragma unroll
    for (int k = 0; k < 8; k++) {
        bool mk = (i1[k] == t1);
        mm1[k] = mk;
        i2[k] = conds ? (mk ? updidxs : i1[k]) : i1[k];
    }
    lm = -i2[0];
    #pragma unroll
    for (int k = 1; k < 8; k++) lm = fmaxf(lm, -i2[k]);
    sred[tid] = lm; __syncthreads();
    for (int st = 128; st > 0; st >>= 1) {
        if (tid < st) sred[tid] = fmaxf(sred[tid], sred[tid + st]);
        __syncthreads();
    }
    const float t2 = sred[0]; __syncthreads();

    const int conde = (!condq) && (!conds);
    unsigned long long best = 0ull;
    #pragma unroll
    for (int k = 0; k < 8; k++) {
        int m = k * 256 + tid;
        bool m2 = (i2[k] == t2);
        float i3 = conde ? (m2 ? r : i2[k]) : i2[k];
        g_idx[m] = i3;
        unsigned char act = 0;
        if (conde && m2)            act = 3;
        else if (conds && mm1[k])   act = 2;
        else if (condq && !mq[k])   act = 1;
        g_action[m] = act;
        unsigned long long p = pack_vm(i3, m);
        if (p > best) best = p;
    }
    spk[tid] = best; __syncthreads();
    for (int st = 128; st > 0; st >>= 1) {
        if (tid < st) spk[tid] = max(spk[tid], spk[tid + st]);
        __syncthreads();
    }
    if (tid == 0) {
        int li = (int)(0xFFFFFFFFu - (unsigned)(spk[0] & 0xFFFFFFFFull));
        g_li = li;
        out[(size_t)B_ * F_ + b] = g_idx[li];   // importances[b]
    }
    __syncthreads();
    // materialize upd_mem_q = memory[mi]*(1-c) + s*c (before any row gets overwritten)
    const float* memrow = g_mem + (size_t)mi * F_;
    for (int f = tid; f < F_; f += 256)
        g_updq[f] = __fadd_rn(__fmul_rn(memrow[f], one_m_c), __fmul_rn(s[f], c));
}

// apply actions, emit targets[b], fused scan for step b+1. grid: 2048 blocks (one per row)
__global__ void k_apply(int b, int do_next,
                        const float* __restrict__ states, float* __restrict__ out) {
    const int m = blockIdx.x;
    const int act = g_action[m];
    const int li = g_li;
    const bool isLi = (m == li);
    if (act == 0 && !do_next && !isLi) return;

    float* row = g_mem + (size_t)m * F_;
    const float* upds  = g_upds + (size_t)b * F_;
    const float* s     = states + ((size_t)b * T_ + (T_ - 1)) * F_;
    const float* snext = states + ((size_t)(b + 1) * T_ + (T_ - 1)) * F_;
    int any = 0;
    for (int f = threadIdx.x; f < F_; f += 256) {
        float v;
        if (act == 0)      v = row[f];
        else if (act == 1) v = g_updq[f];
        else if (act == 2) v = upds[f];
        else               v = s[f];
        if (act) row[f] = v;
        if (isLi) out[(size_t)b * F_ + f] = v;   // targets[b]
        if (do_next) {
            float cp = comp_fn(v, snext[f]);
            any |= (cp >= EPS_);
            if (f == F_ - 1) atomicMax(&g_packed[b + 1], pack_vm(cp, m));
        }
    }
    if (do_next) {
        any = __syncthreads_or(any);
        if (threadIdx.x == 0 && any) atomicOr(&g_flagq[b + 1], 1);
    }
}

// ---------------- launch ----------------
extern "C" void kernel_launch(void* const* d_in, const int* in_sizes, int n_in,
                              void* d_out, int out_size) {
    const float* states = (const float*)d_in[0];   // (64,128,1024)
    const float* mr     = (const float*)d_in[1];   // (64,512,1024)
    const float* memin  = (const float*)d_in[2];   // (2048,1024)
    const float* index  = (const float*)d_in[3];   // (2048,1)
    float* out = (float*)d_out;                    // targets(64*1024) ++ importances(64)

    k_init<<<8, 256>>>(index);
    k_pre<<<dim3(32, B_), 256>>>(states, mr);
    k_copyscan<<<M_, 256>>>(memin, states);
    for (int b = 0; b < B_; b++) {
        k_idx<<<1, 256>>>(b, states, out);
        k_apply<<<M_, 256>>>(b, (b < B_ - 1) ? 1 : 0, states, out);
    }
}

// round 5
// speedup vs baseline: 1.3556x; 1.3475x over previous
#include <cuda_runtime.h>
#include <cstdint>

#define B_ 64
#define T_ 128
#define F_ 1024
#define S_ 512
#define M_ 2048
#define EPS_ 0.45f
#define NB 128
#define NT 256
#define RPB (M_ / NB)   // 16 rows per block

// ---------------- device scratch (static, no allocation) ----------------
__device__ float g_mem[M_ * F_];              // carry: memory (8 MB)
__device__ float g_idxbuf[2][M_];             // carry: index (ping-pong)
__device__ float g_lc[2][M_];                 // memory[:, -1] (ping-pong)
__device__ float g_upds[B_ * F_];             // precomputed upd_mem_s per step
__device__ float g_updidxs[B_];               // precomputed upd_idx_s per step
__device__ unsigned long long g_packed[B_];   // per-step cq argmax (value<<32 | ~m)
__device__ int g_flagq[B_];                   // per-step cond_q
__device__ int g_flags[B_];                   // per-step cond_s
__device__ unsigned long long g_arrive;       // grid barrier
__device__ unsigned long long g_release;

// ---------------- helpers ----------------
__device__ __forceinline__ float comp_fn(float x, float s) {
    float d  = __fsub_rn(x, s);
    float t  = __fadd_rn(__fmul_rn(0.2f, d), 0.5f);
    float hs = fminf(fmaxf(t, 0.0f), 1.0f);
    return __fsub_rn(0.5f, hs);
}
__device__ __forceinline__ unsigned fenc(float x) {
    unsigned u = __float_as_uint(x);
    return (u & 0x80000000u) ? ~u : (u | 0x80000000u);
}
__device__ __forceinline__ float fdec(unsigned u) {
    unsigned v = (u & 0x80000000u) ? (u & 0x7FFFFFFFu) : ~u;
    return __uint_as_float(v);
}
__device__ __forceinline__ unsigned long long pack_vm(float v, int m) {
    return ((unsigned long long)fenc(__fadd_rn(v, 0.0f)) << 32) |
           (unsigned long long)(0xFFFFFFFFu - (unsigned)m);
}

// software grid barrier (all NB blocks co-resident by construction)
__device__ __forceinline__ void gridbar(unsigned long long gen) {
    __syncthreads();
    if (threadIdx.x == 0) {
        __threadfence();
        unsigned long long t = atomicAdd(&g_arrive, 1ull);
        if (t == gen * NB - 1ull) {
            atomicExch(&g_release, gen);
        } else {
            volatile unsigned long long* rel = &g_release;
            while (*rel < gen) { }
        }
        __threadfence();
    }
    __syncthreads();
}

__global__ void k_reset() {
    if (threadIdx.x == 0) { g_arrive = 0ull; g_release = 0ull; }
}

// ---------------- reductions ----------------
__device__ __forceinline__ float blk_maxf(float v, float* sred) {
    int tid = threadIdx.x;
    sred[tid] = v; __syncthreads();
    for (int st = NT / 2; st > 0; st >>= 1) {
        if (tid < st) sred[tid] = fmaxf(sred[tid], sred[tid + st]);
        __syncthreads();
    }
    float r = sred[0]; __syncthreads();
    return r;
}
__device__ __forceinline__ unsigned long long blk_maxu(unsigned long long v,
                                                       unsigned long long* spk) {
    int tid = threadIdx.x;
    spk[tid] = v; __syncthreads();
    for (int st = NT / 2; st > 0; st >>= 1) {
        if (tid < st) spk[tid] = max(spk[tid], spk[tid + st]);
        __syncthreads();
    }
    unsigned long long r = spk[0]; __syncthreads();
    return r;
}

// ---------------- the persistent kernel ----------------
__global__ void __launch_bounds__(NT, 1) mega(
    const float* __restrict__ states, const float* __restrict__ mr,
    const float* __restrict__ memin, const float* __restrict__ index,
    float* __restrict__ out)
{
    __shared__ float sred[NT];
    __shared__ unsigned long long spk[NT];
    __shared__ __align__(16) float s_updq[F_];
    __shared__ unsigned char s_act[RPB];
    __shared__ float s_i1mi;
    __shared__ float smx[NT], sma[NT];

    const int bid = blockIdx.x, tid = threadIdx.x;
    unsigned long long gen = 0;

    // ============ INIT (block 0) ============
    if (bid == 0) {
        if (tid < B_) { g_packed[tid] = 0ull; g_flagq[tid] = 0; g_flags[tid] = 0; }
        for (int m = tid; m < M_; m += NT) g_idxbuf[0][m] = index[m];
    }

    // ============ PRE: (b, chunk) tasks, 2048 total ============
    {
        const int tx = tid & 31, ty = tid >> 5;
        for (int i = 0; i < 16; i++) {
            int task = bid * 16 + i;
            int b = task >> 5, j = task & 31;
            const float* s = states + ((size_t)b * T_ + (T_ - 1)) * F_;
            const int f = j * 32 + tx;
            const float sf = s[f];
            const float* mrb = mr + (size_t)b * S_ * F_;

            float mx = -3.402823466e38f, ma = 0.0f;
            int any = 0;
            for (int ri = ty; ri < S_; ri += 8) {
                float v  = mrb[(size_t)ri * F_ + f];
                float cp = comp_fn(v, sf);
                any |= (cp >= EPS_);
                ma = fmaxf(ma, fabsf(cp));
                mx = fmaxf(mx, v);
            }
            smx[tid] = mx; sma[tid] = ma;
            int anyb = __syncthreads_or(any);
            if (ty == 0) {
                float amx = smx[tx], ama = sma[tx];
                #pragma unroll
                for (int g = 1; g < 8; g++) {
                    amx = fmaxf(amx, smx[g * 32 + tx]);
                    ama = fmaxf(ama, sma[g * 32 + tx]);
                }
                float cs = __fmul_rn(sqrtf((float)S_), ama);
                g_upds[(size_t)b * F_ + f] =
                    __fadd_rn(__fmul_rn(amx, cs), __fmul_rn(sf, __fsub_rn(1.0f, cs)));
                if (f == F_ - 1) {
                    float mr0 = mrb[F_ - 1];
                    g_updidxs[b] = __fadd_rn(__fmul_rn(mr0, cs),
                                             __fmul_rn(sf, __fsub_rn(1.0f, cs)));
                }
                if (tx == 0 && anyb) atomicOr(&g_flags[b], 1);
            }
            __syncthreads();
        }
    }

    // ============ COPY memin -> g_mem fused with step-0 scan ============
    {
        const float* s0 = states + (size_t)(T_ - 1) * F_;
        float4 s0v = ((const float4*)s0)[tid];
        unsigned long long pk = 0ull; int any = 0;
        for (int i = 0; i < RPB; i++) {
            int m = bid * RPB + i;
            float4 v = ((const float4*)(memin + (size_t)m * F_))[tid];
            ((float4*)(g_mem + (size_t)m * F_))[tid] = v;
            float c0 = comp_fn(v.x, s0v.x), c1 = comp_fn(v.y, s0v.y);
            float c2 = comp_fn(v.z, s0v.z), c3 = comp_fn(v.w, s0v.w);
            any |= (c0 >= EPS_) | (c1 >= EPS_) | (c2 >= EPS_) | (c3 >= EPS_);
            if (tid == NT - 1) {
                g_lc[0][m] = v.w;
                unsigned long long p = pack_vm(c3, m);
                if (p > pk) pk = p;
            }
        }
        int anyb = __syncthreads_or(any);
        if (tid == 0 && anyb) atomicOr(&g_flagq[0], 1);
        if (tid == NT - 1 && pk) atomicMax(&g_packed[0], pk);
    }
    gen++; gridbar(gen);

    // ============ main sequential loop ============
    for (int b = 0; b < B_; b++) {
        const float* s = states + ((size_t)b * T_ + (T_ - 1)) * F_;
        const int rd = b & 1, wr = rd ^ 1;
        const float r = s[F_ - 1];
        const int condq = g_flagq[b];
        const int conds = g_flags[b];
        unsigned long long pk0 = g_packed[b];
        const float c  = fdec((unsigned)(pk0 >> 32));
        const int   mi = (int)(0xFFFFFFFFu - (unsigned)(pk0 & 0xFFFFFFFFull));
        const float one_m_c = __fsub_rn(1.0f, c);
        const float idxmi = g_idxbuf[rd][mi];
        const float updq_i = __fadd_rn(__fmul_rn(idxmi, one_m_c), __fmul_rn(r, c));
        const float updidxs = g_updidxs[b];

        // ---- phase B (replicated in every block) ----
        const float* lcr  = g_lc[rd];
        const float* idxr = g_idxbuf[rd];
        float i1[8]; unsigned char mq[8];
        #pragma unroll
        for (int k = 0; k < 8; k++) {
            int m = k * NT + tid;
            float iv  = idxr[m];
            float cqm = comp_fn(lcr[m], r);
            bool maskq = (cqm == c);
            mq[k] = maskq;
            i1[k] = condq ? (maskq ? iv : updq_i) : iv;
        }
        float lm = -i1[0];
        #pragma unroll
        for (int k = 1; k < 8; k++) lm = fmaxf(lm, -i1[k]);
        const float t1 = blk_maxf(lm, sred);

        if (tid == (mi & (NT - 1))) s_i1mi = i1[mi >> 8];  // covered by t2's syncs

        float i2[8]; unsigned char mm1[8];
        #pragma unroll
        for (int k = 0; k < 8; k++) {
            bool mk = (i1[k] == t1);
            mm1[k] = mk;
            i2[k] = conds ? (mk ? updidxs : i1[k]) : i1[k];
        }
        lm = -i2[0];
        #pragma unroll
        for (int k = 1; k < 8; k++) lm = fmaxf(lm, -i2[k]);
        const float t2 = blk_maxf(lm, sred);

        const int conde = (!condq) && (!conds);
        unsigned long long best = 0ull;
        #pragma unroll
        for (int k = 0; k < 8; k++) {
            int m = k * NT + tid;
            bool m2 = (i2[k] == t2);
            float i3 = conde ? (m2 ? r : i2[k]) : i2[k];
            unsigned char act = 0;
            if (conde && m2)          act = 3;
            else if (conds && mm1[k]) act = 2;
            else if (condq && !mq[k]) act = 1;
            if ((m >> 4) == bid) {             // own row
                g_idxbuf[wr][m] = i3;
                s_act[m & (RPB - 1)] = act;
            }
            unsigned long long p = pack_vm(i3, m);
            if (p > best) best = p;
        }
        unsigned long long bpk = blk_maxu(best, spk);
        const int li = (int)(0xFFFFFFFFu - (unsigned)(bpk & 0xFFFFFFFFull));
        if (bid == 0 && tid == 0)
            out[(size_t)B_ * F_ + b] = fdec((unsigned)(bpk >> 32));  // importances[b]

        // upd_mem_q into shared (reads g_mem[mi]; safe unless row mi rewritten this step)
        if (condq) {
            const float* memrow = g_mem + (size_t)mi * F_;
            for (int f = tid; f < F_; f += NT)
                s_updq[f] = __fadd_rn(__fmul_rn(memrow[f], one_m_c),
                                      __fmul_rn(s[f], c));
        }
        __syncthreads();  // s_act / s_updq / s_i1mi visible block-wide

        // rare conflict: row mi itself gets action 2 -> need a mid barrier
        bool need_bar = condq && conds && (s_i1mi == t1);
        if (need_bar) { gen++; gridbar(gen); }

        // ---- phase A (own 16 rows) ----
        const int do_next = (b < B_ - 1);
        const float* snext = states + ((size_t)(b + 1) * T_ + (T_ - 1)) * F_;
        float4 s4 = ((const float4*)s)[tid];
        float4 sn4 = do_next ? ((const float4*)snext)[tid] : s4;
        float4 u4 = conds ? ((const float4*)(g_upds + (size_t)b * F_))[tid] : s4;
        float4 q4 = condq ? ((const float4*)s_updq)[tid] : s4;

        int any = 0; unsigned long long pk = 0ull;
        for (int i = 0; i < RPB; i++) {
            int m = bid * RPB + i;
            int act = s_act[i];
            float4 v;
            if (act == 0)      v = ((const float4*)(g_mem + (size_t)m * F_))[tid];
            else if (act == 1) v = q4;
            else if (act == 2) v = u4;
            else               v = s4;
            if (act) ((float4*)(g_mem + (size_t)m * F_))[tid] = v;
            if (m == li) ((float4*)(out + (size_t)b * F_))[tid] = v;  // targets[b]
            if (do_next) {
                float c0 = comp_fn(v.x, sn4.x), c1 = comp_fn(v.y, sn4.y);
                float c2 = comp_fn(v.z, sn4.z), c3 = comp_fn(v.w, sn4.w);
                any |= (c0 >= EPS_) | (c1 >= EPS_) | (c2 >= EPS_) | (c3 >= EPS_);
                if (tid == NT - 1) {
                    g_lc[wr][m] = v.w;
                    unsigned long long p = pack_vm(c3, m);
                    if (p > pk) pk = p;
                }
            }
        }
        if (do_next) {
            int anyb = __syncthreads_or(any);
            if (tid == 0 && anyb) atomicOr(&g_flagq[b + 1], 1);
            if (tid == NT - 1 && pk) atomicMax(&g_packed[b + 1], pk);
        }
        gen++; gridbar(gen);
    }
}

// ---------------- launch ----------------
extern "C" void kernel_launch(void* const* d_in, const int* in_sizes, int n_in,
                              void* d_out, int out_size) {
    const float* states = (const float*)d_in[0];   // (64,128,1024)
    const float* mr     = (const float*)d_in[1];   // (64,512,1024)
    const float* memin  = (const float*)d_in[2];   // (2048,1024)
    const float* index  = (const float*)d_in[3];   // (2048,1)
    float* out = (float*)d_out;                    // targets(64*1024) ++ importances(64)

    k_reset<<<1, 32>>>();
    mega<<<NB, NT>>>(states, mr, memin, index, out);
}

// round 6
// speedup vs baseline: 1.7484x; 1.2897x over previous
#include <cuda_runtime.h>
#include <cstdint>

#define B_ 64
#define T_ 128
#define F_ 1024
#define S_ 512
#define M_ 2048
#define EPS_ 0.45f
#define NB 128
#define NT 1024

typedef unsigned long long u64;
typedef unsigned u32;

// ---------------- device scratch (static, no allocation) ----------------
__device__ float g_qpool[B_][F_];      // materialized upd_mem_q per step
__device__ float g_upds[B_ * F_];      // precomputed upd_mem_s per step
__device__ float g_updidxs[B_];        // precomputed upd_idx_s per step
__device__ int   g_flags[B_];          // per-step cond_s
__device__ int   g_flagq0;             // step-0 cond_q
__device__ u64   g_arrive, g_release;  // grid barrier

// ---------------- helpers ----------------
__device__ __forceinline__ float comp_fn(float x, float s) {
    float d  = __fsub_rn(x, s);
    float t  = __fadd_rn(__fmul_rn(0.2f, d), 0.5f);
    float hs = fminf(fmaxf(t, 0.0f), 1.0f);
    return __fsub_rn(0.5f, hs);
}
// raw order-preserving float->u32 (bijective)
__device__ __forceinline__ u32 fenc(float x) {
    u32 u = __float_as_uint(x);
    return (u & 0x80000000u) ? ~u : (u | 0x80000000u);
}
__device__ __forceinline__ float fdec(u32 u) {
    u32 v = (u & 0x80000000u) ? (u & 0x7FFFFFFFu) : ~u;
    return __uint_as_float(v);
}
// pack (value, first-index) for argmax via max; normalize -0 -> +0
__device__ __forceinline__ u64 pack_vm(float v, int m) {
    return ((u64)fenc(__fadd_rn(v, 0.0f)) << 32) |
           (u64)(0xFFFFFFFFu - (u32)m);
}

// class id -> row pointer (no table, pure arithmetic)
__device__ __forceinline__ const float* cls_ptr(int id,
        const float* __restrict__ memin, const float* __restrict__ states) {
    if (id < 2048) return memin + (size_t)id * F_;
    if (id < 2112) return g_qpool[id - 2048];
    if (id < 2176) return g_upds + (size_t)(id - 2112) * F_;
    return states + ((size_t)(id - 2176) * T_ + (T_ - 1)) * F_;
}

__global__ void k_reset() {
    int t = threadIdx.x;
    if (t == 0) { g_arrive = 0ull; g_release = 0ull; g_flagq0 = 0; }
    if (t < B_) g_flags[t] = 0;
}

// ---------------- the persistent kernel ----------------
__global__ void __launch_bounds__(NT, 1) mega(
    const float* __restrict__ states, const float* __restrict__ mr,
    const float* __restrict__ memin, const float* __restrict__ index,
    float* __restrict__ out)
{
    __shared__ float s_idx[M_];             // per-row idx (8 KB)
    __shared__ float s_lc[M_];              // per-row last column (8 KB)
    __shared__ unsigned short s_cls[M_];    // per-row class id (4 KB)
    __shared__ unsigned short s_live[2240]; // live class list
    __shared__ u32 s_bm[70];                // live bitmap (2240 bits)
    __shared__ u64 s_red[32];               // reduction scratch
    __shared__ int s_nlive;
    __shared__ int s_flags_s[B_];
    __shared__ float s_updidxs_s[B_], s_updsl_s[B_];

    const int bid = blockIdx.x, tid = threadIdx.x;

    // ============ PRE: per (step, half) column reductions over mr ============
    {
        const int b = bid >> 1, half = bid & 1;
        const int col = half * 512 + (tid & 511);
        const int rp = tid >> 9;
        const float* s = states + ((size_t)b * T_ + (T_ - 1)) * F_;
        const float sf = s[col];
        const float* mrb = mr + (size_t)b * S_ * F_;

        float mx = -3.402823466e38f, ma = 0.0f;
        int any = 0;
        #pragma unroll 4
        for (int ri = rp; ri < S_; ri += 2) {
            float v  = mrb[(size_t)ri * F_ + col];
            float cp = comp_fn(v, sf);
            any |= (cp >= EPS_);
            ma = fmaxf(ma, fabsf(cp));
            mx = fmaxf(mx, v);
        }
        s_idx[tid] = mx;   // scratch reuse
        s_lc[tid]  = ma;
        int anyb = __syncthreads_or(any);
        if (tid < 512) {
            float amx = fmaxf(s_idx[tid], s_idx[tid + 512]);
            float ama = fmaxf(s_lc[tid],  s_lc[tid + 512]);
            float cs = __fmul_rn(sqrtf((float)S_), ama);
            // monotone in mr (cs>=0): max of blend = blend of column max
            g_upds[(size_t)b * F_ + col] =
                __fadd_rn(__fmul_rn(amx, cs), __fmul_rn(sf, __fsub_rn(1.0f, cs)));
            if (col == F_ - 1) {
                float mr0 = mrb[F_ - 1];     // mr[0, -1]
                g_updidxs[b] = __fadd_rn(__fmul_rn(mr0, cs),
                                         __fmul_rn(sf, __fsub_rn(1.0f, cs)));
            }
        }
        if (tid == 0 && anyb) atomicOr(&g_flags[b], 1);
        __syncthreads();
    }

    // ============ step-0 cond_q scan over memin ============
    {
        const float* s0 = states + (size_t)(T_ - 1) * F_;
        float s0v = s0[tid];
        int any = 0;
        #pragma unroll
        for (int i = 0; i < 16; i++) {
            int row = bid * 16 + i;
            any |= (comp_fn(memin[(size_t)row * F_ + tid], s0v) >= EPS_);
        }
        int anyb = __syncthreads_or(any);
        if (tid == 0 && anyb) atomicOr(&g_flagq0, 1);
    }

    // ============ single grid barrier, then only block 0 continues ============
    __syncthreads();
    if (tid == 0) {
        __threadfence();
        u64 t = atomicAdd(&g_arrive, 1ull);
        if (t == (u64)NB - 1ull) {
            atomicExch(&g_release, 1ull);
        } else {
            volatile u64* rel = &g_release;
            while (*rel < 1ull) { }
        }
        __threadfence();
    }
    __syncthreads();
    if (bid != 0) return;

    // ============ init the sequential loop state (all in smem) ============
    #pragma unroll
    for (int k = 0; k < 2; k++) {
        int m = tid + k * 1024;
        s_idx[m] = index[m];
        s_lc[m]  = memin[(size_t)m * F_ + (F_ - 1)];
        s_cls[m] = (unsigned short)m;
    }
    if (tid < B_) {
        s_flags_s[tid]   = g_flags[tid];
        s_updidxs_s[tid] = g_updidxs[tid];
        s_updsl_s[tid]   = g_upds[(size_t)tid * F_ + (F_ - 1)];
    }
    int condq = g_flagq0;
    __syncthreads();

    const int lane = tid & 31, wid = tid >> 5;

    // -------- per-step loop --------
    for (int b = 0; b < B_; b++) {
        const float* s = states + ((size_t)b * T_ + (T_ - 1)) * F_;
        const float sv = s[tid];
        const float r  = s[F_ - 1];
        const int conds = s_flags_s[b];

        // ---- cq argmax (packed) ----
        float cq0 = comp_fn(s_lc[tid], r);
        float cq1 = comp_fn(s_lc[tid + 1024], r);
        u64 pk = max(pack_vm(cq0, tid), pack_vm(cq1, tid + 1024));
        #pragma unroll
        for (int o = 16; o; o >>= 1) pk = max(pk, __shfl_down_sync(0xffffffffu, pk, o));
        if (lane == 0) s_red[wid] = pk;
        __syncthreads();
        if (wid == 0) {
            pk = s_red[lane];
            #pragma unroll
            for (int o = 16; o; o >>= 1) pk = max(pk, __shfl_down_sync(0xffffffffu, pk, o));
            if (lane == 0) s_red[0] = pk;
        }
        __syncthreads();
        pk = s_red[0];
        __syncthreads();

        const float c  = fdec((u32)(pk >> 32));
        const int   mi = (int)(0xFFFFFFFFu - (u32)pk);
        const float idxmi = s_idx[mi];      // broadcast reads, before any write
        const float lcmi  = s_lc[mi];
        const int   clsmi = s_cls[mi];
        const float omc = __fsub_rn(1.0f, c);
        const float updq_i = __fadd_rn(__fmul_rn(idxmi, omc), __fmul_rn(r, c));
        const float updq_l = __fadd_rn(__fmul_rn(lcmi,  omc), __fmul_rn(r, c));
        const float updidxs = s_updidxs_s[b];
        const float upds_l  = s_updsl_s[b];

        // ---- idx chain (2 rows per thread) ----
        const bool mqa = (cq0 == c), mqb = (cq1 == c);
        const float iva = s_idx[tid], ivb = s_idx[tid + 1024];
        const float i1a = condq ? (mqa ? iva : updq_i) : iva;
        const float i1b = condq ? (mqb ? ivb : updq_i) : ivb;

        // t1 = max(-idx1)
        u64 tk = ((u64)max(fenc(-i1a), fenc(-i1b))) << 32;
        #pragma unroll
        for (int o = 16; o; o >>= 1) tk = max(tk, __shfl_down_sync(0xffffffffu, tk, o));
        if (lane == 0) s_red[wid] = tk;
        __syncthreads();
        if (wid == 0) {
            tk = s_red[lane];
            #pragma unroll
            for (int o = 16; o; o >>= 1) tk = max(tk, __shfl_down_sync(0xffffffffu, tk, o));
            if (lane == 0) s_red[0] = tk;
        }
        __syncthreads();
        const float t1 = fdec((u32)(s_red[0] >> 32));
        __syncthreads();

        const bool mm1a = (i1a == t1), mm1b = (i1b == t1);
        const float i2a = conds ? (mm1a ? updidxs : i1a) : i1a;
        const float i2b = conds ? (mm1b ? updidxs : i1b) : i1b;

        // t2 = max(-idx2)
        tk = ((u64)max(fenc(-i2a), fenc(-i2b))) << 32;
        #pragma unroll
        for (int o = 16; o; o >>= 1) tk = max(tk, __shfl_down_sync(0xffffffffu, tk, o));
        if (lane == 0) s_red[wid] = tk;
        __syncthreads();
        if (wid == 0) {
            tk = s_red[lane];
            #pragma unroll
            for (int o = 16; o; o >>= 1) tk = max(tk, __shfl_down_sync(0xffffffffu, tk, o));
            if (lane == 0) s_red[0] = tk;
        }
        __syncthreads();
        const float t2 = fdec((u32)(s_red[0] >> 32));
        __syncthreads();

        const bool conde = (!condq) && (!conds);

        // ---- final idx, class & lc updates (own rows only -> no races) ----
        u64 pli;
        {
            bool m2 = (i2a == t2);
            float i3 = conde ? (m2 ? r : i2a) : i2a;
            int nc = s_cls[tid]; float nl = s_lc[tid];
            if (condq && !mqa) { nc = 2048 + b; nl = updq_l; }
            if (conds && mm1a) { nc = 2112 + b; nl = upds_l; }
            if (conde && m2)   { nc = 2176 + b; nl = r; }
            s_idx[tid] = i3; s_cls[tid] = (unsigned short)nc; s_lc[tid] = nl;
            pli = pack_vm(i3, tid);
        }
        {
            int m = tid + 1024;
            bool m2 = (i2b == t2);
            float i3 = conde ? (m2 ? r : i2b) : i2b;
            int nc = s_cls[m]; float nl = s_lc[m];
            if (condq && !mqb) { nc = 2048 + b; nl = updq_l; }
            if (conds && mm1b) { nc = 2112 + b; nl = upds_l; }
            if (conde && m2)   { nc = 2176 + b; nl = r; }
            s_idx[m] = i3; s_cls[m] = (unsigned short)nc; s_lc[m] = nl;
            pli = max(pli, pack_vm(i3, m));
        }

        // ---- leader argmax ----
        #pragma unroll
        for (int o = 16; o; o >>= 1) pli = max(pli, __shfl_down_sync(0xffffffffu, pli, o));
        if (lane == 0) s_red[wid] = pli;
        __syncthreads();
        if (wid == 0) {
            pli = s_red[lane];
            #pragma unroll
            for (int o = 16; o; o >>= 1) pli = max(pli, __shfl_down_sync(0xffffffffu, pli, o));
            if (lane == 0) s_red[0] = pli;
        }
        __syncthreads();
        pli = s_red[0];
        __syncthreads();
        const int li = (int)(0xFFFFFFFFu - (u32)pli);
        if (tid == 0) out[(size_t)B_ * F_ + b] = fdec((u32)(pli >> 32)); // importances

        // ---- materialize upd_mem_q (only if referenced this step) ----
        if (condq) {
            const float* p = cls_ptr(clsmi, memin, states);
            g_qpool[b][tid] = __fadd_rn(__fmul_rn(p[tid], omc), __fmul_rn(sv, c));
        }
        __syncthreads();  // qpool + s_cls writes visible block-wide

        // ---- targets[b] = row li's class vector ----
        {
            int tc = s_cls[li];
            const float* p = cls_ptr(tc, memin, states);
            out[(size_t)b * F_ + tid] = p[tid];
        }

        // ---- next-step cond_q: any over live classes x F ----
        if (b < B_ - 1) {
            if (tid < 70) s_bm[tid] = 0u;
            if (tid == 0) s_nlive = 0;
            __syncthreads();
            #pragma unroll
            for (int k = 0; k < 2; k++) {
                int id = s_cls[tid + k * 1024];
                u32 w = (u32)id >> 5, bit = 1u << (id & 31);
                if (!(s_bm[w] & bit)) atomicOr(&s_bm[w], bit);
            }
            __syncthreads();
            if (tid < 70) {
                u32 w = s_bm[tid];
                while (w) {
                    int bp = __ffs(w) - 1; w &= w - 1;
                    int pos = atomicAdd(&s_nlive, 1);
                    s_live[pos] = (unsigned short)(tid * 32 + bp);
                }
            }
            __syncthreads();
            const float* snext = states + ((size_t)(b + 1) * T_ + (T_ - 1)) * F_;
            float snv = snext[tid];
            int any = 0;
            const int K = s_nlive;
            for (int j = 0; j < K; j++) {
                const float* p = cls_ptr(s_live[j], memin, states);
                any |= (comp_fn(p[tid], snv) >= EPS_);
            }
            condq = __syncthreads_or(any);
        }
    }
}

// ---------------- launch ----------------
extern "C" void kernel_launch(void* const* d_in, const int* in_sizes, int n_in,
                              void* d_out, int out_size) {
    const float* states = (const float*)d_in[0];   // (64,128,1024)
    const float* mr     = (const float*)d_in[1];   // (64,512,1024)
    const float* memin  = (const float*)d_in[2];   // (2048,1024)
    const float* index  = (const float*)d_in[3];   // (2048,1)
    float* out = (float*)d_out;                    // targets(64*1024) ++ importances(64)

    k_reset<<<1, 128>>>();
    mega<<<NB, NT>>>(states, mr, memin, index, out);
}

// round 7
// speedup vs baseline: 3.0878x; 1.7661x over previous
#include <cuda_runtime.h>
#include <cstdint>

#define B_ 64
#define T_ 128
#define F_ 1024
#define S_ 512
#define M_ 2048
#define EPS_ 0.45f
#define NB 128
#define NT 1024

typedef unsigned long long u64;
typedef unsigned u32;

// ---------------- device scratch (static, no allocation) ----------------
__device__ float g_qpool[B_][F_];      // materialized upd_mem_q per step
__device__ float g_upds[B_ * F_];      // precomputed upd_mem_s per step
__device__ float g_updidxs[B_];        // precomputed upd_idx_s per step
__device__ float g_lc0[M_];            // memin[:, -1] (written by workers)
__device__ int   g_flags[B_];          // per-step cond_s
__device__ int   g_flagq0;             // step-0 cond_q
__device__ int   g_readyS[B_];         // ==2 when step b's pre-data ready
__device__ int   g_readyQ;             // ==NB-1 when memin scan done

// ---------------- helpers ----------------
__device__ __forceinline__ float comp_fn(float x, float s) {
    float d  = __fsub_rn(x, s);
    float t  = __fadd_rn(__fmul_rn(0.2f, d), 0.5f);
    float hs = fminf(fmaxf(t, 0.0f), 1.0f);
    return __fsub_rn(0.5f, hs);
}
__device__ __forceinline__ u32 fenc(float x) {
    u32 u = __float_as_uint(x);
    return (u & 0x80000000u) ? ~u : (u | 0x80000000u);
}
__device__ __forceinline__ float fdec(u32 u) {
    u32 v = (u & 0x80000000u) ? (u & 0x7FFFFFFFu) : ~u;
    return __uint_as_float(v);
}

// class id -> immutable row pointer (pure arithmetic)
__device__ __forceinline__ const float* cls_ptr(int id,
        const float* __restrict__ memin, const float* __restrict__ states) {
    if (id < 2048) return memin + (size_t)id * F_;
    if (id < 2112) return g_qpool[id - 2048];
    if (id < 2176) return g_upds + (size_t)(id - 2112) * F_;
    return states + ((size_t)(id - 2176) * T_ + (T_ - 1)) * F_;
}

__global__ void k_reset() {
    int t = threadIdx.x;
    if (t < B_) { g_readyS[t] = 0; g_flags[t] = 0; }
    if (t == 0) { g_readyQ = 0; g_flagq0 = 0; }
}

// block argmax with first-index tie-break; values pre-encoded (fenc, normalized)
__device__ __forceinline__ u64 blk_argmax(u32 v0, u32 v1, int tid, int lane, int wid,
                                          u64* s_r64, int slot) {
    u32 vm = max(v0, v1);
    u32 wm = __reduce_max_sync(0xffffffffu, vm);
    u32 idx = (v0 == wm) ? (u32)tid : ((v1 == wm) ? (u32)tid + 1024u : 0xffffffffu);
    u32 wi = __reduce_min_sync(0xffffffffu, idx);
    if (lane == 0) s_r64[wid] = ((u64)wm << 32) | (u64)(0xffffffffu - wi);
    __syncthreads();
    if (wid == 0) {
        u64 p = s_r64[lane];
        u32 hv = (u32)(p >> 32);
        u32 g  = __reduce_max_sync(0xffffffffu, hv);
        u32 lo = (hv == g) ? (u32)p : 0u;
        u32 gl = __reduce_max_sync(0xffffffffu, lo);
        if (lane == 0) s_r64[32 + slot] = ((u64)g << 32) | gl;
    }
    __syncthreads();
    return s_r64[32 + slot];
}

// block max of encoded u32
__device__ __forceinline__ u32 blk_maxu32(u32 v, int lane, int wid, u32* s_ru, int slot) {
    u32 wm = __reduce_max_sync(0xffffffffu, v);
    if (lane == 0) s_ru[wid] = wm;
    __syncthreads();
    if (wid == 0) {
        u32 g = __reduce_max_sync(0xffffffffu, s_ru[lane]);
        if (lane == 0) s_ru[32 + slot] = g;
    }
    __syncthreads();
    return s_ru[32 + slot];
}

// ---------------- persistent kernel ----------------
__global__ void __launch_bounds__(NT, 1) mega(
    const float* __restrict__ states, const float* __restrict__ mr,
    const float* __restrict__ memin, const float* __restrict__ index,
    float* __restrict__ out)
{
    __shared__ float s_idx[M_];
    __shared__ float s_lc[M_];
    __shared__ unsigned short s_cls[M_];
    __shared__ unsigned short s_live[2240];
    __shared__ u32 s_bm[70];
    __shared__ u64 s_r64[34];
    __shared__ u32 s_ru[34];
    __shared__ int s_nlive;
    __shared__ float sh_r;
    __shared__ float s_scrA[NT], s_scrB[NT];

    const int bid = blockIdx.x, tid = threadIdx.x;
    const int lane = tid & 31, wid = tid >> 5;

    // ================= WORKERS (bid 1..127) =================
    if (bid != 0) {
        // ---- memin share: rows [(w-1)*17, ...) + lc0 + flagq0 ----
        {
            const float* s0 = states + (size_t)(T_ - 1) * F_;
            float s0v = s0[tid];
            int start = (bid - 1) * 17, end = min(start + 17, M_);
            int any = 0;
            for (int row = start; row < end; row++) {
                float v = memin[(size_t)row * F_ + tid];
                if (tid == F_ - 1) g_lc0[row] = v;
                any |= (comp_fn(v, s0v) >= EPS_);
            }
            int anyb = __syncthreads_or(any);
            __threadfence();
            __syncthreads();
            if (tid == 0) {
                if (anyb) atomicOr(&g_flagq0, 1);
                __threadfence();
                atomicAdd(&g_readyQ, 1);
            }
        }
        // ---- PRE tasks: worker w does task w-1; worker 1 also task 127 ----
        for (int pass = 0; pass < 2; pass++) {
            int task;
            if (pass == 0) task = bid - 1;
            else if (bid == 1) task = 127;
            else break;
            const int b = task >> 1, half = task & 1;
            const int col = half * 512 + (tid & 511);
            const int rp = tid >> 9;
            const float* s = states + ((size_t)b * T_ + (T_ - 1)) * F_;
            const float sf = s[col];
            const float* mrb = mr + (size_t)b * S_ * F_;

            float mx = -3.402823466e38f, ma = 0.0f;
            int any = 0;
            #pragma unroll 8
            for (int ri = rp; ri < S_; ri += 2) {
                float v  = mrb[(size_t)ri * F_ + col];
                float cp = comp_fn(v, sf);
                any |= (cp >= EPS_);
                ma = fmaxf(ma, fabsf(cp));
                mx = fmaxf(mx, v);
            }
            s_scrA[tid] = mx; s_scrB[tid] = ma;
            int anyb = __syncthreads_or(any);
            if (tid < 512) {
                float amx = fmaxf(s_scrA[tid], s_scrA[tid + 512]);
                float ama = fmaxf(s_scrB[tid], s_scrB[tid + 512]);
                float cs = __fmul_rn(sqrtf((float)S_), ama);
                g_upds[(size_t)b * F_ + col] =
                    __fadd_rn(__fmul_rn(amx, cs), __fmul_rn(sf, __fsub_rn(1.0f, cs)));
                if (col == F_ - 1) {
                    float mr0 = mrb[F_ - 1];     // mr[0, -1]
                    g_updidxs[b] = __fadd_rn(__fmul_rn(mr0, cs),
                                             __fmul_rn(sf, __fsub_rn(1.0f, cs)));
                }
            }
            __threadfence();
            __syncthreads();
            if (tid == 0) {
                if (anyb) atomicOr(&g_flags[b], 1);
                __threadfence();
                atomicAdd(&g_readyS[b], 1);
            }
            __syncthreads();
        }
        return;
    }

    // ================= CONSUMER (block 0) =================
    #pragma unroll
    for (int k = 0; k < 2; k++) {
        int m = tid + k * 1024;
        s_idx[m] = index[m];
        s_cls[m] = (unsigned short)m;
    }
    // wait for memin scan (flagq0 + lc0)
    if (tid == 0) {
        volatile int* rq = &g_readyQ;
        while (*rq < NB - 1) { }
        __threadfence();
    }
    __syncthreads();
    int condq = g_flagq0;
    #pragma unroll
    for (int k = 0; k < 2; k++) {
        int m = tid + k * 1024;
        s_lc[m] = g_lc0[m];
    }
    float sv = states[(size_t)(T_ - 1) * F_ + tid];
    if (tid == F_ - 1) sh_r = sv;
    __syncthreads();

    for (int b = 0; b < B_; b++) {
        // prefetch next step's s row (feeds cond-scan + next iteration)
        const float* snrow = states + ((size_t)((b < B_ - 1) ? b + 1 : 0) * T_ + (T_ - 1)) * F_;
        float snv = snrow[tid];

        // wait for this step's precomputed data
        if (tid == 0) {
            volatile int* rs = &g_readyS[b];
            while (*rs < 2) { }
            __threadfence();
        }
        __syncthreads();
        const int conds = g_flags[b];
        const float updidxs = g_updidxs[b];
        const float upds_l  = g_upds[(size_t)b * F_ + (F_ - 1)];
        const float r = sh_r;

        const float lc0v = s_lc[tid],  lc1v = s_lc[tid + 1024];
        const float iv0  = s_idx[tid], iv1  = s_idx[tid + 1024];

        float i1a, i1b;
        bool mqa = false, mqb = false;
        float c = 0.0f, omc = 0.0f;
        int clsmi = 0;
        float qv_in = 0.0f;

        if (condq) {
            float cq0 = comp_fn(lc0v, r);
            float cq1 = comp_fn(lc1v, r);
            u64 pk = blk_argmax(fenc(__fadd_rn(cq0, 0.0f)),
                                fenc(__fadd_rn(cq1, 0.0f)),
                                tid, lane, wid, s_r64, 0);
            c = fdec((u32)(pk >> 32));
            const int mi = (int)(0xffffffffu - (u32)pk);
            const float idxmi = s_idx[mi];     // broadcast reads (pre-write)
            const float lcmi  = s_lc[mi];
            clsmi = s_cls[mi];
            qv_in = cls_ptr(clsmi, memin, states)[tid];  // early LDG for qpool
            omc = __fsub_rn(1.0f, c);
            const float updq_i = __fadd_rn(__fmul_rn(idxmi, omc), __fmul_rn(r, c));
            mqa = (cq0 == c); mqb = (cq1 == c);
            i1a = mqa ? iv0 : updq_i;
            i1b = mqb ? iv1 : updq_i;
        } else {
            i1a = iv0; i1b = iv1;
        }
        const float updq_l = condq
            ? __fadd_rn(__fmul_rn(s_lc[(int)0], 0.0f), 0.0f) : 0.0f; // placeholder (recomputed below)

        float i2a, i2b;
        bool mm1a = false, mm1b = false;
        if (conds) {
            u32 tv = max(fenc(-i1a), fenc(-i1b));
            const float t1 = fdec(blk_maxu32(tv, lane, wid, s_ru, 0));
            mm1a = (i1a == t1); mm1b = (i1b == t1);
            i2a = mm1a ? updidxs : i1a;
            i2b = mm1b ? updidxs : i1b;
        } else {
            i2a = i1a; i2b = i1b;
            if (condq) __syncthreads();  // order broadcast reads vs writes below
        }

        const bool conde = (!condq) && (!conds);
        float i3a, i3b;
        bool m2a = false, m2b = false;
        if (conde) {
            u32 tv = max(fenc(-i2a), fenc(-i2b));
            const float t2 = fdec(blk_maxu32(tv, lane, wid, s_ru, 1));
            m2a = (i2a == t2); m2b = (i2b == t2);
            i3a = m2a ? r : i2a;
            i3b = m2b ? r : i2b;
        } else {
            i3a = i2a; i3b = i2b;
        }

        // ---- own-row class / lc / idx updates (no cross-thread writes) ----
        // recompute updq_l properly (last column of qpool class)
        float updq_last = 0.0f;
        if (condq) {
            // lc of mi's class, blended: identical op order to qpool[b][1023]
            // (lcmi captured only under condq above; reload via broadcast-safe reg)
        }
        int nc0 = s_cls[tid], nc1 = s_cls[tid + 1024];
        float nl0 = lc0v, nl1 = lc1v;
        if (condq) {
            // updq last column value
            // note: s_lc[mi] was read above into lcmi only inside the branch; redo:
            ;
        }
        // -- to keep registers tidy, recompute the two shared per-step scalars here --
        // (values are block-uniform; computed identically in every thread)
        {
            if (condq) {
                // lcmi is needed; it was read in the condq branch. Recover via qv_in?
                ;
            }
        }
        // gates
        if (condq) {
            // updq_l = lcmi*omc + r*c ; lcmi == qv_in's source row last col, but we
            // need the scalar: thread F_-1's qv_in IS that element; broadcast via smem.
            if (tid == F_ - 1) s_scrA[0] = qv_in;   // class(mi) last column
        }
        if (condq) __syncthreads();                  // broadcast s_scrA[0]
        if (condq) {
            updq_last = __fadd_rn(__fmul_rn(s_scrA[0], omc), __fmul_rn(r, c));
            if (!mqa) { nc0 = 2048 + b; nl0 = updq_last; }
            if (!mqb) { nc1 = 2048 + b; nl1 = updq_last; }
        }
        if (conds) {
            if (mm1a) { nc0 = 2112 + b; nl0 = upds_l; }
            if (mm1b) { nc1 = 2112 + b; nl1 = upds_l; }
        }
        if (conde) {
            if (m2a) { nc0 = 2176 + b; nl0 = r; }
            if (m2b) { nc1 = 2176 + b; nl1 = r; }
        }
        s_idx[tid] = i3a; s_cls[tid] = (unsigned short)nc0; s_lc[tid] = nl0;
        s_idx[tid + 1024] = i3b; s_cls[tid + 1024] = (unsigned short)nc1; s_lc[tid + 1024] = nl1;

        // ---- leader argmax over i3 ----
        u64 pli = blk_argmax(fenc(__fadd_rn(i3a, 0.0f)),
                             fenc(__fadd_rn(i3b, 0.0f)),
                             tid, lane, wid, s_r64, 1);
        const int li = (int)(0xffffffffu - (u32)pli);
        if (tid == 0) out[(size_t)B_ * F_ + b] = fdec((u32)(pli >> 32)); // importances

        // ---- qpool materialization + bitmap zero, then barrier ----
        if (condq)
            g_qpool[b][tid] = __fadd_rn(__fmul_rn(qv_in, omc), __fmul_rn(sv, c));
        if (tid < 70) s_bm[tid] = 0u;
        if (tid == 0) s_nlive = 0;
        __syncthreads();  // cls writes + qpool STG + bitmap zero visible

        // ---- targets[b] (overlap load with bitmap build) ----
        const int tc = s_cls[li];
        const float tv = cls_ptr(tc, memin, states)[tid];

        if (b < B_ - 1) {
            // warp-dedup'd bitmap ORs
            u32 p0 = __match_any_sync(0xffffffffu, nc0);
            if ((__ffs(p0) - 1) == lane) atomicOr(&s_bm[nc0 >> 5], 1u << (nc0 & 31));
            u32 p1 = __match_any_sync(0xffffffffu, nc1);
            if ((__ffs(p1) - 1) == lane) atomicOr(&s_bm[nc1 >> 5], 1u << (nc1 & 31));
        }
        out[(size_t)b * F_ + tid] = tv;

        if (b < B_ - 1) {
            __syncthreads();
            if (tid < 70) {
                u32 wbits = s_bm[tid];
                while (wbits) {
                    int bp = __ffs(wbits) - 1; wbits &= wbits - 1;
                    int pos = atomicAdd(&s_nlive, 1);
                    s_live[pos] = (unsigned short)(tid * 32 + bp);
                }
            }
            __syncthreads();
            int any = 0;
            const int K = s_nlive;
            for (int j = 0; j < K; j++) {
                const float* p = cls_ptr(s_live[j], memin, states);
                any |= (comp_fn(p[tid], snv) >= EPS_);
            }
            if (tid == F_ - 1) sh_r = snv;
            condq = __syncthreads_or(any);
            sv = snv;
        }
    }
}

// ---------------- launch ----------------
extern "C" void kernel_launch(void* const* d_in, const int* in_sizes, int n_in,
                              void* d_out, int out_size) {
    const float* states = (const float*)d_in[0];   // (64,128,1024)
    const float* mr     = (const float*)d_in[1];   // (64,512,1024)
    const float* memin  = (const float*)d_in[2];   // (2048,1024)
    const float* index  = (const float*)d_in[3];   // (2048,1)
    float* out = (float*)d_out;                    // targets(64*1024) ++ importances(64)

    k_reset<<<1, 128>>>();
    mega<<<NB, NT>>>(states, mr, memin, index, out);
}

// round 8
// speedup vs baseline: 3.1267x; 1.0126x over previous
#include <cuda_runtime.h>
#include <cstdint>

#define B_ 64
#define T_ 128
#define F_ 1024
#define S_ 512
#define M_ 2048
#define EPS_ 0.45f
#define NB 128
#define NT 1024

typedef unsigned long long u64;
typedef unsigned u32;

// ---------------- device scratch (static, no allocation) ----------------
__device__ float g_qpool[B_][F_];      // materialized upd_mem_q per step
__device__ float g_upds[B_ * F_];      // precomputed upd_mem_s per step
__device__ float g_updidxs[B_];        // precomputed upd_idx_s per step
__device__ float g_lc0[M_];            // memin[:, -1] (written by workers)
__device__ int   g_flags[B_];          // per-step cond_s
__device__ int   g_flagq0;             // step-0 cond_q
__device__ int   g_readyS[B_];         // ==2 when step b's pre-data ready
__device__ int   g_readyQ;             // ==NB-1 when memin scan done

// ---------------- helpers ----------------
__device__ __forceinline__ float comp_fn(float x, float s) {
    float d  = __fsub_rn(x, s);
    float t  = __fadd_rn(__fmul_rn(0.2f, d), 0.5f);
    float hs = fminf(fmaxf(t, 0.0f), 1.0f);
    return __fsub_rn(0.5f, hs);
}
__device__ __forceinline__ u32 fenc(float x) {
    u32 u = __float_as_uint(x);
    return (u & 0x80000000u) ? ~u : (u | 0x80000000u);
}
__device__ __forceinline__ float fdec(u32 u) {
    u32 v = (u & 0x80000000u) ? (u & 0x7FFFFFFFu) : ~u;
    return __uint_as_float(v);
}

// class id -> immutable row pointer (pure arithmetic)
__device__ __forceinline__ const float* cls_ptr(int id,
        const float* __restrict__ memin, const float* __restrict__ states) {
    if (id < 2048) return memin + (size_t)id * F_;
    if (id < 2112) return g_qpool[id - 2048];
    if (id < 2176) return g_upds + (size_t)(id - 2112) * F_;
    return states + ((size_t)(id - 2176) * T_ + (T_ - 1)) * F_;
}

__global__ void k_reset() {
    int t = threadIdx.x;
    if (t < B_) { g_readyS[t] = 0; g_flags[t] = 0; }
    if (t == 0) { g_readyQ = 0; g_flagq0 = 0; }
}

// block argmax with first-index tie-break; values pre-encoded (fenc, normalized)
__device__ __forceinline__ u64 blk_argmax(u32 v0, u32 v1, int tid, int lane, int wid,
                                          u64* s_r64, int slot) {
    u32 vm = max(v0, v1);
    u32 wm = __reduce_max_sync(0xffffffffu, vm);
    u32 idx = (v0 == wm) ? (u32)tid : ((v1 == wm) ? (u32)tid + 1024u : 0xffffffffu);
    u32 wi = __reduce_min_sync(0xffffffffu, idx);
    if (lane == 0) s_r64[wid] = ((u64)wm << 32) | (u64)(0xffffffffu - wi);
    __syncthreads();
    if (wid == 0) {
        u64 p = s_r64[lane];
        u32 hv = (u32)(p >> 32);
        u32 g  = __reduce_max_sync(0xffffffffu, hv);
        u32 lo = (hv == g) ? (u32)p : 0u;
        u32 gl = __reduce_max_sync(0xffffffffu, lo);
        if (lane == 0) s_r64[32 + slot] = ((u64)g << 32) | gl;
    }
    __syncthreads();
    return s_r64[32 + slot];
}

// block max of encoded u32
__device__ __forceinline__ u32 blk_maxu32(u32 v, int lane, int wid, u32* s_ru, int slot) {
    u32 wm = __reduce_max_sync(0xffffffffu, v);
    if (lane == 0) s_ru[wid] = wm;
    __syncthreads();
    if (wid == 0) {
        u32 g = __reduce_max_sync(0xffffffffu, s_ru[lane]);
        if (lane == 0) s_ru[32 + slot] = g;
    }
    __syncthreads();
    return s_ru[32 + slot];
}

// ---------------- persistent kernel ----------------
__global__ void __launch_bounds__(NT, 1) mega(
    const float* __restrict__ states, const float* __restrict__ mr,
    const float* __restrict__ memin, const float* __restrict__ index,
    float* __restrict__ out)
{
    __shared__ float s_idx[M_];
    __shared__ float s_lc[M_];
    __shared__ unsigned short s_cls[M_];
    __shared__ unsigned short s_live[2240];
    __shared__ u32 s_bm[70];
    __shared__ u64 s_r64[34];
    __shared__ u32 s_ru[34];
    __shared__ int s_nlive;
    __shared__ float sh_r;
    __shared__ float s_scrA[NT], s_scrB[NT];

    const int bid = blockIdx.x, tid = threadIdx.x;
    const int lane = tid & 31, wid = tid >> 5;

    // ================= WORKERS (bid 1..127) =================
    if (bid != 0) {
        // ---- memin share: rows [(w-1)*17, ...) + lc0 + flagq0 ----
        {
            const float* s0 = states + (size_t)(T_ - 1) * F_;
            float s0v = s0[tid];
            int start = (bid - 1) * 17, end = min(start + 17, M_);
            int any = 0;
            for (int row = start; row < end; row++) {
                float v = memin[(size_t)row * F_ + tid];
                if (tid == F_ - 1) g_lc0[row] = v;
                any |= (comp_fn(v, s0v) >= EPS_);
            }
            int anyb = __syncthreads_or(any);
            __threadfence();
            __syncthreads();
            if (tid == 0) {
                if (anyb) atomicOr(&g_flagq0, 1);
                __threadfence();
                atomicAdd(&g_readyQ, 1);
            }
        }
        // ---- PRE tasks: worker w does task w-1; worker 1 also task 127 ----
        for (int pass = 0; pass < 2; pass++) {
            int task;
            if (pass == 0) task = bid - 1;
            else if (bid == 1) task = 127;
            else break;
            const int b = task >> 1, half = task & 1;
            const int col = half * 512 + (tid & 511);
            const int rp = tid >> 9;
            const float* s = states + ((size_t)b * T_ + (T_ - 1)) * F_;
            const float sf = s[col];
            const float* mrb = mr + (size_t)b * S_ * F_;

            float mx = -3.402823466e38f, ma = 0.0f;
            int any = 0;
            #pragma unroll 8
            for (int ri = rp; ri < S_; ri += 2) {
                float v  = mrb[(size_t)ri * F_ + col];
                float cp = comp_fn(v, sf);
                any |= (cp >= EPS_);
                ma = fmaxf(ma, fabsf(cp));
                mx = fmaxf(mx, v);
            }
            s_scrA[tid] = mx; s_scrB[tid] = ma;
            int anyb = __syncthreads_or(any);
            if (tid < 512) {
                float amx = fmaxf(s_scrA[tid], s_scrA[tid + 512]);
                float ama = fmaxf(s_scrB[tid], s_scrB[tid + 512]);
                float cs = __fmul_rn(sqrtf((float)S_), ama);
                g_upds[(size_t)b * F_ + col] =
                    __fadd_rn(__fmul_rn(amx, cs), __fmul_rn(sf, __fsub_rn(1.0f, cs)));
                if (col == F_ - 1) {
                    float mr0 = mrb[F_ - 1];     // mr[0, -1]
                    g_updidxs[b] = __fadd_rn(__fmul_rn(mr0, cs),
                                             __fmul_rn(sf, __fsub_rn(1.0f, cs)));
                }
            }
            __threadfence();
            __syncthreads();
            if (tid == 0) {
                if (anyb) atomicOr(&g_flags[b], 1);
                __threadfence();
                atomicAdd(&g_readyS[b], 1);
            }
            __syncthreads();
        }
        return;
    }

    // ================= CONSUMER (block 0) =================
    #pragma unroll
    for (int k = 0; k < 2; k++) {
        int m = tid + k * 1024;
        s_idx[m] = index[m];
        s_cls[m] = (unsigned short)m;
    }
    // wait for memin scan (flagq0 + lc0)
    if (tid == 0) {
        volatile int* rq = &g_readyQ;
        while (*rq < NB - 1) { }
        __threadfence();
    }
    __syncthreads();
    int condq = g_flagq0;
    #pragma unroll
    for (int k = 0; k < 2; k++) {
        int m = tid + k * 1024;
        s_lc[m] = g_lc0[m];
    }
    float sv = states[(size_t)(T_ - 1) * F_ + tid];
    if (tid == F_ - 1) sh_r = sv;
    __syncthreads();

    for (int b = 0; b < B_; b++) {
        // prefetch next step's s row (feeds cond-scan + next iteration)
        const float* snrow = states + ((size_t)((b < B_ - 1) ? b + 1 : 0) * T_ + (T_ - 1)) * F_;
        float snv = snrow[tid];

        // wait for this step's precomputed data
        if (tid == 0) {
            volatile int* rs = &g_readyS[b];
            while (*rs < 2) { }
            __threadfence();
        }
        __syncthreads();
        const int conds = g_flags[b];
        const float updidxs = g_updidxs[b];
        const float upds_l  = g_upds[(size_t)b * F_ + (F_ - 1)];
        const float r = sh_r;

        const float lc0v = s_lc[tid],  lc1v = s_lc[tid + 1024];
        const float iv0  = s_idx[tid], iv1  = s_idx[tid + 1024];

        float i1a, i1b;
        bool mqa = false, mqb = false;
        float c = 0.0f, omc = 0.0f;
        int clsmi = 0;
        float qv_in = 0.0f;

        if (condq) {
            float cq0 = comp_fn(lc0v, r);
            float cq1 = comp_fn(lc1v, r);
            u64 pk = blk_argmax(fenc(__fadd_rn(cq0, 0.0f)),
                                fenc(__fadd_rn(cq1, 0.0f)),
                                tid, lane, wid, s_r64, 0);
            c = fdec((u32)(pk >> 32));
            const int mi = (int)(0xffffffffu - (u32)pk);
            const float idxmi = s_idx[mi];     // broadcast reads (pre-write)
            const float lcmi  = s_lc[mi];
            clsmi = s_cls[mi];
            qv_in = cls_ptr(clsmi, memin, states)[tid];  // early LDG for qpool
            omc = __fsub_rn(1.0f, c);
            const float updq_i = __fadd_rn(__fmul_rn(idxmi, omc), __fmul_rn(r, c));
            mqa = (cq0 == c); mqb = (cq1 == c);
            i1a = mqa ? iv0 : updq_i;
            i1b = mqb ? iv1 : updq_i;
        } else {
            i1a = iv0; i1b = iv1;
        }
        const float updq_l = condq
            ? __fadd_rn(__fmul_rn(s_lc[(int)0], 0.0f), 0.0f) : 0.0f; // placeholder (recomputed below)

        float i2a, i2b;
        bool mm1a = false, mm1b = false;
        if (conds) {
            u32 tv = max(fenc(-i1a), fenc(-i1b));
            const float t1 = fdec(blk_maxu32(tv, lane, wid, s_ru, 0));
            mm1a = (i1a == t1); mm1b = (i1b == t1);
            i2a = mm1a ? updidxs : i1a;
            i2b = mm1b ? updidxs : i1b;
        } else {
            i2a = i1a; i2b = i1b;
            if (condq) __syncthreads();  // order broadcast reads vs writes below
        }

        const bool conde = (!condq) && (!conds);
        float i3a, i3b;
        bool m2a = false, m2b = false;
        if (conde) {
            u32 tv = max(fenc(-i2a), fenc(-i2b));
            const float t2 = fdec(blk_maxu32(tv, lane, wid, s_ru, 1));
            m2a = (i2a == t2); m2b = (i2b == t2);
            i3a = m2a ? r : i2a;
            i3b = m2b ? r : i2b;
        } else {
            i3a = i2a; i3b = i2b;
        }

        // ---- own-row class / lc / idx updates (no cross-thread writes) ----
        // recompute updq_l properly (last column of qpool class)
        float updq_last = 0.0f;
        if (condq) {
            // lc of mi's class, blended: identical op order to qpool[b][1023]
            // (lcmi captured only under condq above; reload via broadcast-safe reg)
        }
        int nc0 = s_cls[tid], nc1 = s_cls[tid + 1024];
        float nl0 = lc0v, nl1 = lc1v;
        if (condq) {
            // updq last column value
            // note: s_lc[mi] was read above into lcmi only inside the branch; redo:
            ;
        }
        // -- to keep registers tidy, recompute the two shared per-step scalars here --
        // (values are block-uniform; computed identically in every thread)
        {
            if (condq) {
                // lcmi is needed; it was read in the condq branch. Recover via qv_in?
                ;
            }
        }
        // gates
        if (condq) {
            // updq_l = lcmi*omc + r*c ; lcmi == qv_in's source row last col, but we
            // need the scalar: thread F_-1's qv_in IS that element; broadcast via smem.
            if (tid == F_ - 1) s_scrA[0] = qv_in;   // class(mi) last column
        }
        if (condq) __syncthreads();                  // broadcast s_scrA[0]
        if (condq) {
            updq_last = __fadd_rn(__fmul_rn(s_scrA[0], omc), __fmul_rn(r, c));
            if (!mqa) { nc0 = 2048 + b; nl0 = updq_last; }
            if (!mqb) { nc1 = 2048 + b; nl1 = updq_last; }
        }
        if (conds) {
            if (mm1a) { nc0 = 2112 + b; nl0 = upds_l; }
            if (mm1b) { nc1 = 2112 + b; nl1 = upds_l; }
        }
        if (conde) {
            if (m2a) { nc0 = 2176 + b; nl0 = r; }
            if (m2b) { nc1 = 2176 + b; nl1 = r; }
        }
        s_idx[tid] = i3a; s_cls[tid] = (unsigned short)nc0; s_lc[tid] = nl0;
        s_idx[tid + 1024] = i3b; s_cls[tid + 1024] = (unsigned short)nc1; s_lc[tid + 1024] = nl1;

        // ---- leader argmax over i3 ----
        u64 pli = blk_argmax(fenc(__fadd_rn(i3a, 0.0f)),
                             fenc(__fadd_rn(i3b, 0.0f)),
                             tid, lane, wid, s_r64, 1);
        const int li = (int)(0xffffffffu - (u32)pli);
        if (tid == 0) out[(size_t)B_ * F_ + b] = fdec((u32)(pli >> 32)); // importances

        // ---- qpool materialization + bitmap zero, then barrier ----
        if (condq)
            g_qpool[b][tid] = __fadd_rn(__fmul_rn(qv_in, omc), __fmul_rn(sv, c));
        if (tid < 70) s_bm[tid] = 0u;
        if (tid == 0) s_nlive = 0;
        __syncthreads();  // cls writes + qpool STG + bitmap zero visible

        // ---- targets[b] (overlap load with bitmap build) ----
        const int tc = s_cls[li];
        const float tv = cls_ptr(tc, memin, states)[tid];

        if (b < B_ - 1) {
            // warp-dedup'd bitmap ORs
            u32 p0 = __match_any_sync(0xffffffffu, nc0);
            if ((__ffs(p0) - 1) == lane) atomicOr(&s_bm[nc0 >> 5], 1u << (nc0 & 31));
            u32 p1 = __match_any_sync(0xffffffffu, nc1);
            if ((__ffs(p1) - 1) == lane) atomicOr(&s_bm[nc1 >> 5], 1u << (nc1 & 31));
        }
        out[(size_t)b * F_ + tid] = tv;

        if (b < B_ - 1) {
            __syncthreads();
            if (tid < 70) {
                u32 wbits = s_bm[tid];
                while (wbits) {
                    int bp = __ffs(wbits) - 1; wbits &= wbits - 1;
                    int pos = atomicAdd(&s_nlive, 1);
                    s_live[pos] = (unsigned short)(tid * 32 + bp);
                }
            }
            __syncthreads();
            int any = 0;
            const int K = s_nlive;
            for (int j = 0; j < K; j++) {
                const float* p = cls_ptr(s_live[j], memin, states);
                any |= (comp_fn(p[tid], snv) >= EPS_);
            }
            if (tid == F_ - 1) sh_r = snv;
            condq = __syncthreads_or(any);
            sv = snv;
        }
    }
}

// ---------------- launch ----------------
extern "C" void kernel_launch(void* const* d_in, const int* in_sizes, int n_in,
                              void* d_out, int out_size) {
    const float* states = (const float*)d_in[0];   // (64,128,1024)
    const float* mr     = (const float*)d_in[1];   // (64,512,1024)
    const float* memin  = (const float*)d_in[2];   // (2048,1024)
    const float* index  = (const float*)d_in[3];   // (2048,1)
    float* out = (float*)d_out;                    // targets(64*1024) ++ importances(64)

    k_reset<<<1, 128>>>();
    mega<<<NB, NT>>>(states, mr, memin, index, out);
}

// round 9
// speedup vs baseline: 3.9049x; 1.2489x over previous
#include <cuda_runtime.h>
#include <cstdint>

#define B_ 64
#define T_ 128
#define F_ 1024
#define S_ 512
#define M_ 2048
#define EPS_ 0.45f
#define NB 128
#define NT 1024
#define FULLM 0xffffffffu

typedef unsigned long long u64;
typedef unsigned u32;

// ---------------- device scratch (static, no allocation) ----------------
__device__ float g_qpool[B_][F_];      // materialized upd_mem_q per step
__device__ float g_upds[B_ * F_];      // precomputed upd_mem_s per step
__device__ float g_updidxs[B_];        // precomputed upd_idx_s per step
__device__ float g_lc0[M_];            // memin[:, -1]
__device__ int   g_flags[B_];          // per-step cond_s
__device__ int   g_flagq0;             // step-0 cond_q
__device__ int   g_readyS[B_];         // ==2 when step b's pre-data ready
__device__ int   g_readyQ;             // ==NB-1 when memin scan done

// ---------------- helpers ----------------
__device__ __forceinline__ float comp_fn(float x, float s) {
    float d  = __fsub_rn(x, s);
    float t  = __fadd_rn(__fmul_rn(0.2f, d), 0.5f);
    float hs = fminf(fmaxf(t, 0.0f), 1.0f);
    return __fsub_rn(0.5f, hs);
}
__device__ __forceinline__ u32 fenc(float x) {
    u32 u = __float_as_uint(x);
    return (u & 0x80000000u) ? ~u : (u | 0x80000000u);
}
__device__ __forceinline__ float fdec(u32 u) {
    u32 v = (u & 0x80000000u) ? (u & 0x7FFFFFFFu) : ~u;
    return __uint_as_float(v);
}
__device__ __forceinline__ u64 pack_gm(u32 venc, u32 gmin) {
    return ((u64)venc << 32) | (u64)(0xffffffffu - gmin);
}

// class id -> immutable row pointer
__device__ __forceinline__ const float* cls_ptr(int id,
        const float* __restrict__ memin, const float* __restrict__ states) {
    if (id < 2048) return memin + (size_t)id * F_;
    if (id < 2112) return g_qpool[id - 2048];
    if (id < 2176) return g_upds + (size_t)(id - 2112) * F_;
    return states + ((size_t)(id - 2176) * T_ + (T_ - 1)) * F_;
}

__global__ void k_reset() {
    int t = threadIdx.x;
    if (t < B_) { g_readyS[t] = 0; g_flags[t] = 0; }
    if (t == 0) { g_readyQ = 0; g_flagq0 = 0; }
}

// ---------------- block reductions (generic path) ----------------
__device__ __forceinline__ u64 blk_max64(u64 v, int lane, int wid, u64* s64) {
    #pragma unroll
    for (int o = 16; o; o >>= 1) v = max(v, __shfl_xor_sync(FULLM, v, o));
    if (lane == 0) s64[wid] = v;
    __syncthreads();
    if (wid == 0) {
        u64 p = s64[lane];
        #pragma unroll
        for (int o = 16; o; o >>= 1) p = max(p, __shfl_xor_sync(FULLM, p, o));
        if (lane == 0) s64[32] = p;
    }
    __syncthreads();
    return s64[32];
}
__device__ __forceinline__ u32 blk_maxu(u32 v, int lane, int wid, u32* su) {
    u32 wm = __reduce_max_sync(FULLM, v);
    if (lane == 0) su[wid] = wm;
    __syncthreads();
    if (wid == 0) { u32 g = __reduce_max_sync(FULLM, su[lane]); if (lane == 0) su[32] = g; }
    __syncthreads();
    return su[32];
}
__device__ __forceinline__ u32 blk_minu(u32 v, int lane, int wid, u32* su) {
    u32 wm = __reduce_min_sync(FULLM, v);
    if (lane == 0) su[wid] = wm;
    __syncthreads();
    if (wid == 0) { u32 g = __reduce_min_sync(FULLM, su[lane]); if (lane == 0) su[32] = g; }
    __syncthreads();
    return su[32];
}

// ---------------- persistent kernel ----------------
__global__ void __launch_bounds__(NT, 1) mega(
    const float* __restrict__ states, const float* __restrict__ mr,
    const float* __restrict__ memin, const float* __restrict__ index,
    float* __restrict__ out)
{
    __shared__ float s_gidx[M_];            // group idx (also worker scratch A)
    __shared__ float s_glc[M_];             // group last-col (worker scratch B)
    __shared__ unsigned short s_gcls[M_];   // group class id
    __shared__ unsigned short s_gmin[M_];   // group min original row
    __shared__ u64 s_r64[33];
    __shared__ u32 s_ru[33];
    __shared__ int s_cnt, s_G, s_clsmi, s_tcls;
    __shared__ float sh_r, s_c, s_imp, s_idxmi, s_lcmi;

    const int bid = blockIdx.x, tid = threadIdx.x;
    const int lane = tid & 31, wid = tid >> 5;

    // ================= WORKERS (bid 1..127) =================
    if (bid != 0) {
        {   // memin scan share (17 rows each) + lc0 + flagq0
            const float* s0 = states + (size_t)(T_ - 1) * F_;
            float s0v = s0[tid];
            int start = (bid - 1) * 17, end = min(start + 17, M_);
            int any = 0;
            for (int row = start; row < end; row++) {
                float v = memin[(size_t)row * F_ + tid];
                if (tid == F_ - 1) g_lc0[row] = v;
                any |= (comp_fn(v, s0v) >= EPS_);
            }
            int anyb = __syncthreads_or(any);
            __threadfence();
            __syncthreads();
            if (tid == 0) {
                if (anyb) atomicOr(&g_flagq0, 1);
                __threadfence();
                atomicAdd(&g_readyQ, 1);
            }
        }
        for (int pass = 0; pass < 2; pass++) {
            int task;
            if (pass == 0) task = bid - 1;
            else if (bid == 1) task = 127;
            else break;
            const int b = task >> 1, half = task & 1;
            const int col = half * 512 + (tid & 511);
            const int rp = tid >> 9;
            const float* s = states + ((size_t)b * T_ + (T_ - 1)) * F_;
            const float sf = s[col];
            const float* mrb = mr + (size_t)b * S_ * F_;

            float mx = -3.402823466e38f, ma = 0.0f;
            int any = 0;
            #pragma unroll 8
            for (int ri = rp; ri < S_; ri += 2) {
                float v  = mrb[(size_t)ri * F_ + col];
                float cp = comp_fn(v, sf);
                any |= (cp >= EPS_);
                ma = fmaxf(ma, fabsf(cp));
                mx = fmaxf(mx, v);
            }
            s_gidx[tid] = mx; s_glc[tid] = ma;
            int anyb = __syncthreads_or(any);
            if (tid < 512) {
                float amx = fmaxf(s_gidx[tid], s_gidx[tid + 512]);
                float ama = fmaxf(s_glc[tid],  s_glc[tid + 512]);
                float cs = __fmul_rn(sqrtf((float)S_), ama);
                g_upds[(size_t)b * F_ + col] =
                    __fadd_rn(__fmul_rn(amx, cs), __fmul_rn(sf, __fsub_rn(1.0f, cs)));
                if (col == F_ - 1) {
                    float mr0 = mrb[F_ - 1];     // mr[0, -1]
                    g_updidxs[b] = __fadd_rn(__fmul_rn(mr0, cs),
                                             __fmul_rn(sf, __fsub_rn(1.0f, cs)));
                }
            }
            __threadfence();
            __syncthreads();
            if (tid == 0) {
                if (anyb) atomicOr(&g_flags[b], 1);
                __threadfence();
                atomicAdd(&g_readyS[b], 1);
            }
            __syncthreads();
        }
        return;
    }

    // ================= CONSUMER (block 0) =================
    #pragma unroll
    for (int k = 0; k < 2; k++) {
        int m = tid + k * 1024;
        s_gidx[m] = index[m];
        s_gcls[m] = (unsigned short)m;
        s_gmin[m] = (unsigned short)m;
    }
    if (tid == 0) {
        volatile int* rq = &g_readyQ;
        while (*rq < NB - 1) { }
        __threadfence();
        s_G = M_;
    }
    __syncthreads();
    int condq = g_flagq0;
    #pragma unroll
    for (int k = 0; k < 2; k++) { int m = tid + k * 1024; s_glc[m] = g_lc0[m]; }
    float sv = states[(size_t)(T_ - 1) * F_ + tid];
    if (tid == F_ - 1) sh_r = sv;
    int prev_qcls = -1; float qprev = 0.0f;
    __syncthreads();

    for (int b = 0; b < B_; b++) {
        const float* snrow = states + ((size_t)((b < B_ - 1) ? b + 1 : b) * T_ + (T_ - 1)) * F_;
        float snv = snrow[tid];

        if (tid == 0) {
            volatile int* rs = &g_readyS[b];
            while (*rs < 2) { }
            __threadfence();
        }
        __syncthreads();
        const int conds = g_flags[b];
        const float updidxs = g_updidxs[b];
        const float upds_l  = g_upds[(size_t)b * F_ + (F_ - 1)];
        const float uv      = g_upds[(size_t)b * F_ + tid];
        const float r = sh_r;
        const int G = s_G;
        const int clsA = 2048 + b, clsB = 2112 + b, clsC = 2176 + b;

        if (G <= 32) {
            // ======== warp-0 chain, no block barriers ========
            if (tid < 32) {
                bool valid = lane < G;
                int   cls  = s_gcls[lane];
                float idxv = s_gidx[lane];
                float lcv  = s_glc[lane];
                u32   gmin = s_gmin[lane];
                float cq = comp_fn(lcv, r);
                float c = 0.f, omc = 0.f, updq_i = 0.f, updq_l = 0.f;
                bool mask = false;
                float i1;
                if (condq) {
                    u64 me = valid ? pack_gm(fenc(__fadd_rn(cq, 0.0f)), gmin) : 0ull;
                    u64 pk = me;
                    #pragma unroll
                    for (int o = 16; o; o >>= 1) pk = max(pk, __shfl_xor_sync(FULLM, pk, o));
                    u32 wb = __ballot_sync(FULLM, valid && me == pk);
                    int wl = __ffs(wb) - 1;
                    c = fdec((u32)(pk >> 32));
                    float idxmi = __shfl_sync(FULLM, idxv, wl);
                    float lcmi  = __shfl_sync(FULLM, lcv,  wl);
                    int   cmi   = __shfl_sync(FULLM, cls,  wl);
                    omc = __fsub_rn(1.0f, c);
                    updq_i = __fadd_rn(__fmul_rn(idxmi, omc), __fmul_rn(r, c));
                    updq_l = __fadd_rn(__fmul_rn(lcmi,  omc), __fmul_rn(r, c));
                    mask = (cq == c);
                    i1 = mask ? idxv : updq_i;
                    if (lane == 0) { s_clsmi = cmi; s_c = c; }
                } else i1 = idxv;

                bool mm1 = false; float i2;
                if (conds) {
                    u32 t1e = __reduce_max_sync(FULLM, valid ? fenc(-i1) : 0u);
                    float t1 = fdec(t1e);
                    mm1 = valid && (i1 == t1);
                    i2 = mm1 ? updidxs : i1;
                } else i2 = i1;

                const bool conde = (!condq) && (!conds);
                bool m2 = false; float i3;
                if (conde) {
                    u32 t2e = __reduce_max_sync(FULLM, valid ? fenc(-i2) : 0u);
                    float t2 = fdec(t2e);
                    m2 = valid && (i2 == t2);
                    i3 = m2 ? r : i2;
                } else i3 = i2;

                const bool uB = conds && mm1;
                const bool uC = conde && m2;
                const bool uA = condq && !mask && !uB;
                const bool upd = uA || uB || uC;
                int ncls = cls;
                if (uA) ncls = clsA;
                if (uB) ncls = clsB;
                if (uC) ncls = clsC;

                // leader argmax over i3 (tie: min original row)
                u64 ml = valid ? pack_gm(fenc(__fadd_rn(i3, 0.0f)), gmin) : 0ull;
                u64 pl = ml;
                #pragma unroll
                for (int o = 16; o; o >>= 1) pl = max(pl, __shfl_xor_sync(FULLM, pl, o));
                u32 lb = __ballot_sync(FULLM, valid && ml == pl);
                int ll = __ffs(lb) - 1;
                int tcl = __shfl_sync(FULLM, ncls, ll);
                if (lane == 0) { s_tcls = tcl; s_imp = fdec((u32)(pl >> 32)); }

                // merge + compaction (kept groups are fully unchanged)
                u32 kb = __ballot_sync(FULLM, valid && !upd);
                int pos = __popc(kb & ((1u << lane) - 1));
                u32 bA = __ballot_sync(FULLM, valid && uA);
                u32 bB = __ballot_sync(FULLM, valid && uB);
                u32 bC = __ballot_sync(FULLM, valid && uC);
                u32 mnA = __reduce_min_sync(FULLM, (valid && uA) ? gmin : FULLM);
                u32 mnB = __reduce_min_sync(FULLM, (valid && uB) ? gmin : FULLM);
                u32 mnC = __reduce_min_sync(FULLM, (valid && uC) ? gmin : FULLM);
                __syncwarp();
                if (valid && !upd) {
                    s_gcls[pos] = (unsigned short)cls;
                    s_gidx[pos] = idxv;
                    s_glc[pos]  = lcv;
                    s_gmin[pos] = (unsigned short)gmin;
                }
                if (lane == 0) {
                    int w = __popc(kb);
                    if (bA) { s_gcls[w] = (unsigned short)clsA; s_gidx[w] = updq_i;
                              s_glc[w] = updq_l; s_gmin[w] = (unsigned short)mnA; w++; }
                    if (bB) { s_gcls[w] = (unsigned short)clsB; s_gidx[w] = updidxs;
                              s_glc[w] = upds_l; s_gmin[w] = (unsigned short)mnB; w++; }
                    if (bC) { s_gcls[w] = (unsigned short)clsC; s_gidx[w] = r;
                              s_glc[w] = r; s_gmin[w] = (unsigned short)mnC; w++; }
                    s_G = w;
                }
            }
            __syncthreads();
        } else {
            // ======== generic block path (step 0 / fallback) ========
            const bool v0 = tid < G, v1 = tid + 1024 < G;
            int   cls0 = s_gcls[tid], cls1 = s_gcls[tid + 1024];
            float idx0 = s_gidx[tid], idx1 = s_gidx[tid + 1024];
            float lc0v = s_glc[tid],  lc1v = s_glc[tid + 1024];
            u32   gm0  = s_gmin[tid], gm1  = s_gmin[tid + 1024];
            float cq0 = comp_fn(lc0v, r), cq1 = comp_fn(lc1v, r);
            float c = 0.f, omc = 0.f, updq_i = 0.f, updq_l = 0.f;
            bool mask0 = false, mask1 = false;
            float i1a, i1b;
            if (condq) {
                u64 p0 = v0 ? pack_gm(fenc(__fadd_rn(cq0, 0.0f)), gm0) : 0ull;
                u64 p1 = v1 ? pack_gm(fenc(__fadd_rn(cq1, 0.0f)), gm1) : 0ull;
                u64 pk = blk_max64(max(p0, p1), lane, wid, s_r64);
                c = fdec((u32)(pk >> 32));
                u32 wmin = 0xffffffffu - (u32)pk;
                if (v0 && gm0 == wmin) { s_clsmi = cls0; s_idxmi = idx0; s_lcmi = lc0v; }
                if (v1 && gm1 == wmin) { s_clsmi = cls1; s_idxmi = idx1; s_lcmi = lc1v; }
                if (tid == 0) s_c = c;
                __syncthreads();
                omc = __fsub_rn(1.0f, c);
                updq_i = __fadd_rn(__fmul_rn(s_idxmi, omc), __fmul_rn(r, c));
                updq_l = __fadd_rn(__fmul_rn(s_lcmi,  omc), __fmul_rn(r, c));
                mask0 = (cq0 == c); mask1 = (cq1 == c);
                i1a = mask0 ? idx0 : updq_i;
                i1b = mask1 ? idx1 : updq_i;
            } else { i1a = idx0; i1b = idx1; }

            bool mm1a = false, mm1b = false;
            float i2a, i2b;
            if (conds) {
                u32 tv = max(v0 ? fenc(-i1a) : 0u, v1 ? fenc(-i1b) : 0u);
                float t1 = fdec(blk_maxu(tv, lane, wid, s_ru));
                mm1a = v0 && (i1a == t1); mm1b = v1 && (i1b == t1);
                i2a = mm1a ? updidxs : i1a;
                i2b = mm1b ? updidxs : i1b;
            } else { i2a = i1a; i2b = i1b; }

            const bool conde = (!condq) && (!conds);
            bool m2a = false, m2b = false;
            float i3a, i3b;
            if (conde) {
                u32 tv = max(v0 ? fenc(-i2a) : 0u, v1 ? fenc(-i2b) : 0u);
                float t2 = fdec(blk_maxu(tv, lane, wid, s_ru));
                m2a = v0 && (i2a == t2); m2b = v1 && (i2b == t2);
                i3a = m2a ? r : i2a;
                i3b = m2b ? r : i2b;
            } else { i3a = i2a; i3b = i2b; }

            const bool uB0 = conds && mm1a, uB1 = conds && mm1b;
            const bool uC0 = conde && m2a,  uC1 = conde && m2b;
            const bool uA0 = condq && !mask0 && !uB0, uA1 = condq && !mask1 && !uB1;
            const bool up0 = uA0 || uB0 || uC0, up1 = uA1 || uB1 || uC1;
            int nc0 = cls0, nc1 = cls1;
            if (uA0) nc0 = clsA; if (uB0) nc0 = clsB; if (uC0) nc0 = clsC;
            if (uA1) nc1 = clsA; if (uB1) nc1 = clsB; if (uC1) nc1 = clsC;

            // leader
            {
                u64 p0 = v0 ? pack_gm(fenc(__fadd_rn(i3a, 0.0f)), gm0) : 0ull;
                u64 p1 = v1 ? pack_gm(fenc(__fadd_rn(i3b, 0.0f)), gm1) : 0ull;
                u64 pl = blk_max64(max(p0, p1), lane, wid, s_r64);
                u32 wmin = 0xffffffffu - (u32)pl;
                if (v0 && gm0 == wmin) s_tcls = nc0;
                if (v1 && gm1 == wmin) s_tcls = nc1;
                if (tid == 0) { s_imp = fdec((u32)(pl >> 32)); s_cnt = 0; }
                __syncthreads();
            }
            // merged-class min rows
            u32 mnA = FULLM, mnB = FULLM, mnC = FULLM;
            if (condq) mnA = blk_minu(min((v0 && uA0) ? gm0 : FULLM,
                                          (v1 && uA1) ? gm1 : FULLM), lane, wid, s_ru);
            if (conds) mnB = blk_minu(min((v0 && uB0) ? gm0 : FULLM,
                                          (v1 && uB1) ? gm1 : FULLM), lane, wid, s_ru);
            if (conde) mnC = blk_minu(min((v0 && uC0) ? gm0 : FULLM,
                                          (v1 && uC1) ? gm1 : FULLM), lane, wid, s_ru);
            // compaction via aggregated atomics (order irrelevant; tie-breaks use gmin)
            {
                bool k0 = v0 && !up0;
                u32 bk = __ballot_sync(FULLM, k0);
                if (bk) {
                    int ldr = __ffs(bk) - 1;
                    int base = 0;
                    if (lane == ldr) base = atomicAdd(&s_cnt, __popc(bk));
                    base = __shfl_sync(FULLM, base, ldr);
                    if (k0) {
                        int p = base + __popc(bk & ((1u << lane) - 1));
                        s_gcls[p] = (unsigned short)cls0; s_gidx[p] = idx0;
                        s_glc[p] = lc0v; s_gmin[p] = (unsigned short)gm0;
                    }
                }
                bool k1 = v1 && !up1;
                bk = __ballot_sync(FULLM, k1);
                if (bk) {
                    int ldr = __ffs(bk) - 1;
                    int base = 0;
                    if (lane == ldr) base = atomicAdd(&s_cnt, __popc(bk));
                    base = __shfl_sync(FULLM, base, ldr);
                    if (k1) {
                        int p = base + __popc(bk & ((1u << lane) - 1));
                        s_gcls[p] = (unsigned short)cls1; s_gidx[p] = idx1;
                        s_glc[p] = lc1v; s_gmin[p] = (unsigned short)gm1;
                    }
                }
            }
            __syncthreads();
            if (tid == 0) {
                int w = s_cnt;
                if (mnA != FULLM) { s_gcls[w] = (unsigned short)clsA; s_gidx[w] = updq_i;
                                    s_glc[w] = updq_l; s_gmin[w] = (unsigned short)mnA; w++; }
                if (mnB != FULLM) { s_gcls[w] = (unsigned short)clsB; s_gidx[w] = updidxs;
                                    s_glc[w] = upds_l; s_gmin[w] = (unsigned short)mnB; w++; }
                if (mnC != FULLM) { s_gcls[w] = (unsigned short)clsC; s_gidx[w] = r;
                                    s_glc[w] = r; s_gmin[w] = (unsigned short)mnC; w++; }
                s_G = w;
            }
            __syncthreads();
        }

        // ======== F-wide phase ========
        const int newG = s_G;
        const int tcls = s_tcls;
        if (tid == 0) out[(size_t)B_ * F_ + b] = s_imp;   // importances[b]

        float qv_out = 0.0f;
        if (condq) {
            const float cB = s_c;
            const float omcB = __fsub_rn(1.0f, cB);
            const int clsmi = s_clsmi;
            float src = (clsmi == prev_qcls) ? qprev
                        : cls_ptr(clsmi, memin, states)[tid];
            qv_out = __fadd_rn(__fmul_rn(src, omcB), __fmul_rn(sv, cB));
            g_qpool[b][tid] = qv_out;
        }
        {   // targets[b]
            float tv;
            if (tcls == clsA)           tv = qv_out;
            else if (tcls == clsB)      tv = uv;
            else if (tcls == clsC)      tv = sv;
            else if (tcls == prev_qcls) tv = qprev;
            else                        tv = cls_ptr(tcls, memin, states)[tid];
            out[(size_t)b * F_ + tid] = tv;
        }
        int nextq = 0;
        if (b < B_ - 1) {
            int any = 0;
            for (int j = 0; j < newG; j++) {
                int ccls = s_gcls[j];
                float v;
                if (ccls == clsA)           v = qv_out;
                else if (ccls == clsB)      v = uv;
                else if (ccls == clsC)      v = sv;
                else if (ccls == prev_qcls) v = qprev;
                else                        v = cls_ptr(ccls, memin, states)[tid];
                any |= (comp_fn(v, snv) >= EPS_);
            }
            if (tid == F_ - 1) sh_r = snv;
            nextq = __syncthreads_or(any);
        }
        if (condq) { qprev = qv_out; prev_qcls = clsA; }
        condq = nextq;
        sv = snv;
    }
}

// ---------------- launch ----------------
extern "C" void kernel_launch(void* const* d_in, const int* in_sizes, int n_in,
                              void* d_out, int out_size) {
    const float* states = (const float*)d_in[0];   // (64,128,1024)
    const float* mr     = (const float*)d_in[1];   // (64,512,1024)
    const float* memin  = (const float*)d_in[2];   // (2048,1024)
    const float* index  = (const float*)d_in[3];   // (2048,1)
    float* out = (float*)d_out;                    // targets(64*1024) ++ importances(64)

    k_reset<<<1, 128>>>();
    mega<<<NB, NT>>>(states, mr, memin, index, out);
}

// round 10
// speedup vs baseline: 4.7338x; 1.2123x over previous
#include <cuda_runtime.h>
#include <cstdint>

#define B_ 64
#define T_ 128
#define F_ 1024
#define S_ 512
#define M_ 2048
#define EPS_ 0.45f
#define NB 128
#define NT 1024
#define NSLOT 10
#define FULLM 0xffffffffu

typedef unsigned long long u64;
typedef unsigned u32;
typedef unsigned short u16;
typedef unsigned char u8;

// ---------------- device scratch (static, no allocation) ----------------
__device__ float g_qpool[B_][F_];      // materialized upd_mem_q per step
__device__ float g_upds[B_ * F_];      // precomputed upd_mem_s per step
__device__ float g_updidxs[B_];        // precomputed upd_idx_s per step
__device__ float g_lc0[M_];            // memin[:, -1]
__device__ int   g_flags[B_];          // per-step cond_s
__device__ int   g_flagq0;             // step-0 cond_q
__device__ int   g_scnt[B_];           // per-step chunk arrival count
__device__ int   g_sready[B_];         // step data ready
__device__ int   g_ticket;             // worker chunk dispenser
__device__ int   g_readyQ;             // memin scan done count
// generic-path (big-G) group arrays
__device__ float g_bgidx[M_];
__device__ float g_bglc[M_];
__device__ u16   g_bgcls[M_];
__device__ u16   g_bgmin[M_];

// ---------------- helpers ----------------
__device__ __forceinline__ float comp_fn(float x, float s) {
    float d  = __fsub_rn(x, s);
    float t  = __fadd_rn(__fmul_rn(0.2f, d), 0.5f);
    float hs = fminf(fmaxf(t, 0.0f), 1.0f);
    return __fsub_rn(0.5f, hs);
}
__device__ __forceinline__ u32 fenc(float x) {
    u32 u = __float_as_uint(x);
    return (u & 0x80000000u) ? ~u : (u | 0x80000000u);
}
__device__ __forceinline__ float fdec(u32 u) {
    u32 v = (u & 0x80000000u) ? (u & 0x7FFFFFFFu) : ~u;
    return __uint_as_float(v);
}
__device__ __forceinline__ u64 pack_gm(u32 venc, u32 gmin) {
    return ((u64)venc << 32) | (u64)(0xffffffffu - gmin);
}
__device__ __forceinline__ const float* cls_ptr(int id,
        const float* __restrict__ memin, const float* __restrict__ states) {
    if (id < 2048) return memin + (size_t)id * F_;
    if (id < 2112) return g_qpool[id - 2048];
    if (id < 2176) return g_upds + (size_t)(id - 2112) * F_;
    return states + ((size_t)(id - 2176) * T_ + (T_ - 1)) * F_;
}

__global__ void k_reset() {
    int t = threadIdx.x;
    if (t < B_) { g_flags[t] = 0; g_scnt[t] = 0; g_sready[t] = 0; }
    if (t == 0) { g_ticket = 0; g_readyQ = 0; g_flagq0 = 0; }
}

// ---------------- persistent kernel ----------------
__global__ void __launch_bounds__(NT, 1) mega(
    const float* __restrict__ states, const float* __restrict__ mr,
    const float* __restrict__ memin, const float* __restrict__ index,
    float* __restrict__ out)
{
    __shared__ float s_cache[NSLOT * F_];       // 40KB class-vector cache
    __shared__ float s_gidx[64], s_glc[64];     // small group arrays (warp path)
    __shared__ u16 s_gcls[64], s_gmin16[64];
    __shared__ u8  s_gslot[64], s_gfill[64];
    __shared__ int   s_scalconds[2];            // per-step scalars (double buffer)
    __shared__ float s_scalidx[2], s_scalupl[2];
    __shared__ u64 s_r64[33];
    __shared__ u32 s_ru[33];
    __shared__ int s_G, s_jt, s_misrc, s_micls, s_cnt, s_tcls, s_tk, s_clsmiS;
    __shared__ float sh_r, s_c, s_imp, s_idxmi, s_lcmi;

    const int bid = blockIdx.x, tid = threadIdx.x;
    const int lane = tid & 31, wid = tid >> 5;

    // ================= WORKERS (bid 1..127) =================
    if (bid != 0) {
        {   // memin scan share + lc0 + flagq0
            const float* s0 = states + (size_t)(T_ - 1) * F_;
            float s0v = s0[tid];
            int start = (bid - 1) * 17, end = min(start + 17, M_);
            int any = 0;
            for (int row = start; row < end; row++) {
                float v = memin[(size_t)row * F_ + tid];
                if (tid == F_ - 1) g_lc0[row] = v;
                any |= (comp_fn(v, s0v) >= EPS_);
            }
            int anyb = __syncthreads_or(any);
            __threadfence();
            __syncthreads();
            if (tid == 0) {
                if (anyb) atomicOr(&g_flagq0, 1);
                __threadfence();
                atomicAdd(&g_readyQ, 1);
            }
        }
        // ticket loop: 512 chunks = 64 steps x 8 col-chunks, in step order
        float* scrA = s_cache; float* scrB = s_cache + NT;
        while (true) {
            if (tid == 0) s_tk = atomicAdd(&g_ticket, 1);
            __syncthreads();
            int t = s_tk;
            if (t >= 512) break;
            const int b = t >> 3, ch = t & 7;
            const int col = ch * 128 + (tid & 127);
            const int rg = tid >> 7;   // 8 row groups of 64 rows
            const float* srow = states + ((size_t)b * T_ + (T_ - 1)) * F_;
            const float sf = srow[col];
            const float* mrb = mr + (size_t)b * S_ * F_;
            float mx = -3.402823466e38f, ma = 0.0f; int any2 = 0;
            #pragma unroll 8
            for (int ri = rg; ri < S_; ri += 8) {
                float v  = mrb[(size_t)ri * F_ + col];
                float cp = comp_fn(v, sf);
                any2 |= (cp >= EPS_);
                ma = fmaxf(ma, fabsf(cp));
                mx = fmaxf(mx, v);
            }
            scrA[tid] = mx; scrB[tid] = ma;
            int anyc = __syncthreads_or(any2);
            if (tid < 128) {
                float amx = scrA[tid], ama = scrB[tid];
                #pragma unroll
                for (int g = 1; g < 8; g++) {
                    amx = fmaxf(amx, scrA[g * 128 + tid]);
                    ama = fmaxf(ama, scrB[g * 128 + tid]);
                }
                int cc = ch * 128 + tid;
                float cs = __fmul_rn(sqrtf((float)S_), ama);
                g_upds[(size_t)b * F_ + cc] =
                    __fadd_rn(__fmul_rn(amx, cs), __fmul_rn(sf, __fsub_rn(1.0f, cs)));
                if (cc == F_ - 1) {
                    float mr0 = mrb[F_ - 1];   // mr[0, -1]
                    g_updidxs[b] = __fadd_rn(__fmul_rn(mr0, cs),
                                             __fmul_rn(sf, __fsub_rn(1.0f, cs)));
                }
            }
            __threadfence();
            __syncthreads();
            if (tid == 0) {
                if (anyc) atomicOr(&g_flags[b], 1);
                __threadfence();
                int done = atomicAdd(&g_scnt[b], 1);
                if (done == 7) atomicExch(&g_sready[b], 1);
            }
            __syncthreads();
        }
        return;
    }

    // ================= CONSUMER (block 0) =================
    if (tid == 0) {
        volatile int* rq = &g_readyQ;
        while (*rq < NB - 1) { }
        volatile int* rs = &g_sready[0];
        while (!*rs) { }
        __threadfence();
        s_scalconds[0] = g_flags[0];
        s_scalidx[0]   = g_updidxs[0];
        s_scalupl[0]   = g_upds[F_ - 1];
        s_G = M_;
    }
    __syncthreads();
    #pragma unroll
    for (int k = 0; k < 2; k++) {
        int m = tid + k * 1024;
        g_bgidx[m] = index[m];
        g_bglc[m]  = g_lc0[m];
        g_bgcls[m] = (u16)m;
        g_bgmin[m] = (u16)m;
    }
    float sv = states[(size_t)(T_ - 1) * F_ + tid];
    if (tid == F_ - 1) sh_r = sv;
    int condq = g_flagq0;
    float uv = g_upds[tid];
    __syncthreads();

    for (int b = 0; b < B_; b++) {
        const float* snrow = states + ((size_t)((b < B_ - 1) ? b + 1 : b) * T_ + (T_ - 1)) * F_;
        float snv = snrow[tid];
        const int G = s_G;
        const int conds   = s_scalconds[b & 1];
        const float updidxs = s_scalidx[b & 1];
        const float upds_l  = s_scalupl[b & 1];
        const float r = sh_r;
        const int clsA = 2048 + b, clsB = 2112 + b, clsC = 2176 + b;
        const bool doscan = (b < B_ - 1);
        const bool generic = (G > 32);

        if (!generic) {
            // ---- warp 1: prefetch next step's scalars (overlaps warp 0 chain) ----
            if (wid == 1 && lane == 0 && b + 1 < B_) {
                volatile int* rs = &g_sready[b + 1];
                while (!*rs) { }
                __threadfence();
                int p = (b + 1) & 1;
                s_scalconds[p] = g_flags[b + 1];
                s_scalidx[p]   = g_updidxs[b + 1];
                s_scalupl[p]   = g_upds[(size_t)(b + 1) * F_ + (F_ - 1)];
            }
            // ---- warp 0: group chain ----
            if (wid == 0) {
                bool valid = lane < G;
                int   cls  = valid ? (int)s_gcls[lane] : -1;
                float idxv = valid ? s_gidx[lane] : 0.f;
                float lcv  = valid ? s_glc[lane]  : 0.f;
                u32   gmin = valid ? (u32)s_gmin16[lane] : 0xffffu;
                int   slotv = valid ? (int)s_gslot[lane] : 0xFF;

                float cq = comp_fn(lcv, r);
                float c = 0.f, omc = 0.f, updq_i = 0.f, updq_l = 0.f;
                bool mask = false;
                float i1;
                int wl = 0;
                if (condq) {
                    u64 me = valid ? pack_gm(fenc(__fadd_rn(cq, 0.0f)), gmin) : 0ull;
                    u64 pk = me;
                    #pragma unroll
                    for (int o = 16; o; o >>= 1) pk = max(pk, __shfl_xor_sync(FULLM, pk, o));
                    u32 wb = __ballot_sync(FULLM, valid && me == pk);
                    wl = __ffs(wb) - 1;
                    c = fdec((u32)(pk >> 32));
                    float idxmi = __shfl_sync(FULLM, idxv, wl);
                    float lcmi  = __shfl_sync(FULLM, lcv,  wl);
                    omc = __fsub_rn(1.0f, c);
                    updq_i = __fadd_rn(__fmul_rn(idxmi, omc), __fmul_rn(r, c));
                    updq_l = __fadd_rn(__fmul_rn(lcmi,  omc), __fmul_rn(r, c));
                    mask = (cq == c);
                    i1 = mask ? idxv : updq_i;
                } else i1 = idxv;

                bool mm1 = false; float i2;
                if (conds) {
                    float t1 = fdec(__reduce_max_sync(FULLM, valid ? fenc(-i1) : 0u));
                    mm1 = valid && (i1 == t1);
                    i2 = mm1 ? updidxs : i1;
                } else i2 = i1;

                const bool conde = (!condq) && (!conds);
                bool m2 = false; float i3;
                if (conde) {
                    float t2 = fdec(__reduce_max_sync(FULLM, valid ? fenc(-i2) : 0u));
                    m2 = valid && (i2 == t2);
                    i3 = m2 ? r : i2;
                } else i3 = i2;

                const bool uB = conds && mm1;
                const bool uC = conde && m2;
                const bool uA = condq && !mask && !uB;
                const bool upd = uA || uB || uC;
                int ncls = cls;
                if (uA) ncls = clsA;
                if (uB) ncls = clsB;
                if (uC) ncls = clsC;

                u64 ml = valid ? pack_gm(fenc(__fadd_rn(i3, 0.0f)), gmin) : 0ull;
                u64 pl = ml;
                #pragma unroll
                for (int o = 16; o; o >>= 1) pl = max(pl, __shfl_xor_sync(FULLM, pl, o));
                u32 lb = __ballot_sync(FULLM, valid && ml == pl);
                int ll = __ffs(lb) - 1;

                u32 kb = __ballot_sync(FULLM, valid && !upd);
                int pos = __popc(kb & ((1u << lane) - 1));
                int nk = __popc(kb);
                u32 bA = __ballot_sync(FULLM, valid && uA);
                u32 bB = __ballot_sync(FULLM, valid && uB);
                u32 bC = __ballot_sync(FULLM, valid && uC);
                u32 mnA = __reduce_min_sync(FULLM, (valid && uA) ? gmin : FULLM);
                u32 mnB = __reduce_min_sync(FULLM, (valid && uB) ? gmin : FULLM);
                u32 mnC = __reduce_min_sync(FULLM, (valid && uC) ? gmin : FULLM);
                int idxAe = nk;
                int idxBe = nk + (bA ? 1 : 0);
                int idxCe = nk + (bA ? 1 : 0) + (bB ? 1 : 0);

                if (lane == ll) {
                    s_jt = (!upd) ? pos : (uA ? idxAe : (uB ? idxBe : idxCe));
                    s_imp = fdec((u32)(pl >> 32));
                }
                // used-slot mask: kept groups + protected blend-source slot
                u32 ub = (valid && !upd && slotv < NSLOT) ? (1u << slotv) : 0u;
                ub = __reduce_or_sync(FULLM, ub);
                int wlSlot = 0xFF, wlCls = -1;
                if (condq) {
                    int wlUpd = __shfl_sync(FULLM, upd ? 1 : 0, wl);
                    wlSlot = __shfl_sync(FULLM, slotv, wl);
                    wlCls  = __shfl_sync(FULLM, cls, wl);
                    if (wlUpd && wlSlot < NSLOT) ub |= (1u << wlSlot);
                }
                if (valid && !upd) {
                    s_gcls[pos] = (u16)cls; s_gidx[pos] = i3; s_glc[pos] = lcv;
                    s_gmin16[pos] = (u16)gmin; s_gslot[pos] = (u8)slotv;
                }
                __syncwarp();
                if (lane == 0) {
                    int w = nk;
                    if (bA) { s_gcls[w] = (u16)clsA; s_gidx[w] = updq_i; s_glc[w] = updq_l;
                              s_gmin16[w] = (u16)mnA; s_gslot[w] = 0xFF; w++; }
                    if (bB) { s_gcls[w] = (u16)clsB; s_gidx[w] = updidxs; s_glc[w] = upds_l;
                              s_gmin16[w] = (u16)mnB; s_gslot[w] = 0xFF; w++; }
                    if (bC) { s_gcls[w] = (u16)clsC; s_gidx[w] = r; s_glc[w] = r;
                              s_gmin16[w] = (u16)mnC; s_gslot[w] = 0xFF; w++; }
                    s_G = w;
                    u32 freem = (~ub) & ((1u << NSLOT) - 1u);
                    for (int j = 0; j < w; j++) {
                        if (s_gslot[j] == 0xFF) {
                            if (freem) {
                                int f = __ffs(freem) - 1;
                                freem &= ~(1u << f);
                                s_gslot[j] = (u8)f;
                            }
                            s_gfill[j] = 1;
                        } else s_gfill[j] = 0;
                    }
                    if (condq) {
                        s_micls = wlCls;
                        s_misrc = (wlSlot != 0xFF) ? wlSlot : -1;
                        s_c = c;
                    }
                    if (w > 32) {   // overflow: spill to global for generic path
                        for (int j = 0; j < w; j++) {
                            g_bgcls[j] = s_gcls[j]; g_bgidx[j] = s_gidx[j];
                            g_bglc[j]  = s_glc[j];  g_bgmin[j] = s_gmin16[j];
                        }
                    }
                }
            }
            __syncthreads();   // barrier #1

            // ---- fast F-phase ----
            float qv_out = 0.f;
            if (condq) {
                float cF = s_c, omcF = __fsub_rn(1.0f, cF);
                int msrc = s_misrc;
                float srcv = (msrc >= 0) ? s_cache[msrc * F_ + tid]
                                         : cls_ptr(s_micls, memin, states)[tid];
                qv_out = __fadd_rn(__fmul_rn(srcv, omcF), __fmul_rn(sv, cF));
                g_qpool[b][tid] = qv_out;
            }
            const int nG = s_G, jt = s_jt;
            float tval = 0.f;
            int any = 0;
            for (int j = 0; j < nG; j++) {
                int cls2 = s_gcls[j]; int slot = s_gslot[j]; int fill = s_gfill[j];
                float v;
                if (cls2 == clsA)      v = qv_out;
                else if (cls2 == clsB) v = uv;
                else if (cls2 == clsC) v = sv;
                else if (!fill)        v = s_cache[slot * F_ + tid];
                else                   v = cls_ptr(cls2, memin, states)[tid];
                if (fill && slot != 0xFF) s_cache[slot * F_ + tid] = v;
                if (j == jt) tval = v;
                if (doscan) any |= (comp_fn(v, snv) >= EPS_);
            }
            out[(size_t)b * F_ + tid] = tval;
            if (tid == 0) out[(size_t)B_ * F_ + b] = s_imp;
            float uvn = doscan ? g_upds[(size_t)(b + 1) * F_ + tid] : 0.f;
            if (tid == F_ - 1) sh_r = snv;
            if (doscan) {
                condq = __syncthreads_or(any);
                uv = uvn;
            }
            sv = snv;
        } else {
            // ======== generic block path (step 0 / fallback), groups in global ====
            const bool v0 = tid < G, v1 = tid + 1024 < G;
            int   cls0 = v0 ? (int)g_bgcls[tid] : -1;
            int   cls1 = v1 ? (int)g_bgcls[tid + 1024] : -1;
            float idx0 = v0 ? g_bgidx[tid] : 0.f, idx1 = v1 ? g_bgidx[tid + 1024] : 0.f;
            float lc0v = v0 ? g_bglc[tid] : 0.f,  lc1v = v1 ? g_bglc[tid + 1024] : 0.f;
            u32   gm0 = v0 ? (u32)g_bgmin[tid] : FULLM;
            u32   gm1 = v1 ? (u32)g_bgmin[tid + 1024] : FULLM;
            float cq0 = comp_fn(lc0v, r), cq1 = comp_fn(lc1v, r);
            float c = 0.f, omc = 0.f, updq_i = 0.f, updq_l = 0.f;
            bool mask0 = false, mask1 = false;
            float i1a, i1b;
            if (condq) {
                u64 p0 = v0 ? pack_gm(fenc(__fadd_rn(cq0, 0.0f)), gm0) : 0ull;
                u64 p1 = v1 ? pack_gm(fenc(__fadd_rn(cq1, 0.0f)), gm1) : 0ull;
                u64 v = max(p0, p1);
                #pragma unroll
                for (int o = 16; o; o >>= 1) v = max(v, __shfl_xor_sync(FULLM, v, o));
                if (lane == 0) s_r64[wid] = v;
                __syncthreads();
                if (wid == 0) {
                    u64 p = s_r64[lane];
                    #pragma unroll
                    for (int o = 16; o; o >>= 1) p = max(p, __shfl_xor_sync(FULLM, p, o));
                    if (lane == 0) s_r64[32] = p;
                }
                __syncthreads();
                u64 pk = s_r64[32];
                __syncthreads();
                c = fdec((u32)(pk >> 32));
                u32 wmin = 0xffffffffu - (u32)pk;
                if (v0 && gm0 == wmin) { s_clsmiS = cls0; s_idxmi = idx0; s_lcmi = lc0v; }
                if (v1 && gm1 == wmin) { s_clsmiS = cls1; s_idxmi = idx1; s_lcmi = lc1v; }
                if (tid == 0) s_c = c;
                __syncthreads();
                omc = __fsub_rn(1.0f, c);
                updq_i = __fadd_rn(__fmul_rn(s_idxmi, omc), __fmul_rn(r, c));
                updq_l = __fadd_rn(__fmul_rn(s_lcmi,  omc), __fmul_rn(r, c));
                mask0 = (cq0 == c); mask1 = (cq1 == c);
                i1a = mask0 ? idx0 : updq_i;
                i1b = mask1 ? idx1 : updq_i;
            } else { i1a = idx0; i1b = idx1; }

            bool mm1a = false, mm1b = false;
            float i2a, i2b;
            if (conds) {
                u32 tv = max(v0 ? fenc(-i1a) : 0u, v1 ? fenc(-i1b) : 0u);
                u32 wm = __reduce_max_sync(FULLM, tv);
                if (lane == 0) s_ru[wid] = wm;
                __syncthreads();
                if (wid == 0) { u32 g = __reduce_max_sync(FULLM, s_ru[lane]); if (lane == 0) s_ru[32] = g; }
                __syncthreads();
                float t1 = fdec(s_ru[32]);
                __syncthreads();
                mm1a = v0 && (i1a == t1); mm1b = v1 && (i1b == t1);
                i2a = mm1a ? updidxs : i1a;
                i2b = mm1b ? updidxs : i1b;
            } else { i2a = i1a; i2b = i1b; }

            const bool conde = (!condq) && (!conds);
            bool m2a = false, m2b = false;
            float i3a, i3b;
            if (conde) {
                u32 tv = max(v0 ? fenc(-i2a) : 0u, v1 ? fenc(-i2b) : 0u);
                u32 wm = __reduce_max_sync(FULLM, tv);
                if (lane == 0) s_ru[wid] = wm;
                __syncthreads();
                if (wid == 0) { u32 g = __reduce_max_sync(FULLM, s_ru[lane]); if (lane == 0) s_ru[32] = g; }
                __syncthreads();
                float t2 = fdec(s_ru[32]);
                __syncthreads();
                m2a = v0 && (i2a == t2); m2b = v1 && (i2b == t2);
                i3a = m2a ? r : i2a;
                i3b = m2b ? r : i2b;
            } else { i3a = i2a; i3b = i2b; }

            const bool uB0 = conds && mm1a, uB1 = conds && mm1b;
            const bool uC0 = conde && m2a,  uC1 = conde && m2b;
            const bool uA0 = condq && !mask0 && !uB0, uA1 = condq && !mask1 && !uB1;
            const bool up0 = uA0 || uB0 || uC0, up1 = uA1 || uB1 || uC1;
            int nc0 = cls0, nc1 = cls1;
            if (uA0) nc0 = clsA; if (uB0) nc0 = clsB; if (uC0) nc0 = clsC;
            if (uA1) nc1 = clsA; if (uB1) nc1 = clsB; if (uC1) nc1 = clsC;

            {   // leader
                u64 p0 = v0 ? pack_gm(fenc(__fadd_rn(i3a, 0.0f)), gm0) : 0ull;
                u64 p1 = v1 ? pack_gm(fenc(__fadd_rn(i3b, 0.0f)), gm1) : 0ull;
                u64 v = max(p0, p1);
                #pragma unroll
                for (int o = 16; o; o >>= 1) v = max(v, __shfl_xor_sync(FULLM, v, o));
                if (lane == 0) s_r64[wid] = v;
                __syncthreads();
                if (wid == 0) {
                    u64 p = s_r64[lane];
                    #pragma unroll
                    for (int o = 16; o; o >>= 1) p = max(p, __shfl_xor_sync(FULLM, p, o));
                    if (lane == 0) s_r64[32] = p;
                }
                __syncthreads();
                u64 pl = s_r64[32];
                u32 wmin = 0xffffffffu - (u32)pl;
                if (v0 && gm0 == wmin) s_tcls = nc0;
                if (v1 && gm1 == wmin) s_tcls = nc1;
                if (tid == 0) { s_imp = fdec((u32)(pl >> 32)); s_cnt = 0; }
                __syncthreads();
            }
            u32 mnA = FULLM, mnB = FULLM, mnC = FULLM;
            {
                u32 a = min((v0 && uA0) ? gm0 : FULLM, (v1 && uA1) ? gm1 : FULLM);
                u32 bm = min((v0 && uB0) ? gm0 : FULLM, (v1 && uB1) ? gm1 : FULLM);
                u32 cm = min((v0 && uC0) ? gm0 : FULLM, (v1 && uC1) ? gm1 : FULLM);
                u32 wa = __reduce_min_sync(FULLM, a);
                u32 wb2 = __reduce_min_sync(FULLM, bm);
                u32 wc = __reduce_min_sync(FULLM, cm);
                if (lane == 0) { s_ru[wid] = wa; }
                __syncthreads();
                if (wid == 0) { u32 g = __reduce_min_sync(FULLM, s_ru[lane]); if (lane == 0) s_ru[32] = g; }
                __syncthreads();
                mnA = s_ru[32]; __syncthreads();
                if (lane == 0) { s_ru[wid] = wb2; }
                __syncthreads();
                if (wid == 0) { u32 g = __reduce_min_sync(FULLM, s_ru[lane]); if (lane == 0) s_ru[32] = g; }
                __syncthreads();
                mnB = s_ru[32]; __syncthreads();
                if (lane == 0) { s_ru[wid] = wc; }
                __syncthreads();
                if (wid == 0) { u32 g = __reduce_min_sync(FULLM, s_ru[lane]); if (lane == 0) s_ru[32] = g; }
                __syncthreads();
                mnC = s_ru[32]; __syncthreads();
            }
            // compaction via aggregated atomics into global arrays
            {
                bool k0 = v0 && !up0;
                u32 bk = __ballot_sync(FULLM, k0);
                if (bk) {
                    int ldr = __ffs(bk) - 1;
                    int base = 0;
                    if (lane == ldr) base = atomicAdd(&s_cnt, __popc(bk));
                    base = __shfl_sync(FULLM, base, ldr);
                    if (k0) {
                        int p = base + __popc(bk & ((1u << lane) - 1));
                        g_bgcls[p] = (u16)cls0; g_bgidx[p] = idx0;
                        g_bglc[p] = lc0v; g_bgmin[p] = (u16)gm0;
                    }
                }
                bool k1 = v1 && !up1;
                bk = __ballot_sync(FULLM, k1);
                if (bk) {
                    int ldr = __ffs(bk) - 1;
                    int base = 0;
                    if (lane == ldr) base = atomicAdd(&s_cnt, __popc(bk));
                    base = __shfl_sync(FULLM, base, ldr);
                    if (k1) {
                        int p = base + __popc(bk & ((1u << lane) - 1));
                        g_bgcls[p] = (u16)cls1; g_bgidx[p] = idx1;
                        g_bglc[p] = lc1v; g_bgmin[p] = (u16)gm1;
                    }
                }
            }
            __syncthreads();
            if (tid == 0) {
                int w = s_cnt;
                if (mnA != FULLM) { g_bgcls[w] = (u16)clsA; g_bgidx[w] = updq_i;
                                    g_bglc[w] = updq_l; g_bgmin[w] = (u16)mnA; w++; }
                if (mnB != FULLM) { g_bgcls[w] = (u16)clsB; g_bgidx[w] = updidxs;
                                    g_bglc[w] = upds_l; g_bgmin[w] = (u16)mnB; w++; }
                if (mnC != FULLM) { g_bgcls[w] = (u16)clsC; g_bgidx[w] = r;
                                    g_bglc[w] = r; g_bgmin[w] = (u16)mnC; w++; }
                s_G = w;
                // prefetch next scalars (rare path: serial is fine)
                if (b + 1 < B_) {
                    volatile int* rs = &g_sready[b + 1];
                    while (!*rs) { }
                    __threadfence();
                    int p = (b + 1) & 1;
                    s_scalconds[p] = g_flags[b + 1];
                    s_scalidx[p]   = g_updidxs[b + 1];
                    s_scalupl[p]   = g_upds[(size_t)(b + 1) * F_ + (F_ - 1)];
                }
            }
            __syncthreads();
            // copy compacted groups to smem if small (cache starts empty)
            const int wNew = s_G;
            if (wNew <= 32 && tid < wNew) {
                s_gcls[tid] = g_bgcls[tid]; s_gidx[tid] = g_bgidx[tid];
                s_glc[tid] = g_bglc[tid]; s_gmin16[tid] = g_bgmin[tid];
                s_gslot[tid] = 0xFF; s_gfill[tid] = 0;
            }

            // ---- slow F-phase ----
            float qv_out = 0.f;
            if (condq) {
                float cF = s_c, omcF = __fsub_rn(1.0f, cF);
                float srcv = cls_ptr(s_clsmiS, memin, states)[tid];
                qv_out = __fadd_rn(__fmul_rn(srcv, omcF), __fmul_rn(sv, cF));
                g_qpool[b][tid] = qv_out;
            }
            {
                int tcls = s_tcls;
                float tval;
                if (tcls == clsA)      tval = qv_out;
                else if (tcls == clsB) tval = uv;
                else if (tcls == clsC) tval = sv;
                else tval = cls_ptr(tcls, memin, states)[tid];
                out[(size_t)b * F_ + tid] = tval;
            }
            if (tid == 0) out[(size_t)B_ * F_ + b] = s_imp;
            float uvn = doscan ? g_upds[(size_t)(b + 1) * F_ + tid] : 0.f;
            int any = 0;
            if (doscan) {
                for (int j = 0; j < wNew; j++) {
                    int cls2 = g_bgcls[j];
                    float v;
                    if (cls2 == clsA)      v = qv_out;
                    else if (cls2 == clsB) v = uv;
                    else if (cls2 == clsC) v = sv;
                    else v = cls_ptr(cls2, memin, states)[tid];
                    any |= (comp_fn(v, snv) >= EPS_);
                }
            }
            if (tid == F_ - 1) sh_r = snv;
            if (doscan) {
                condq = __syncthreads_or(any);
                uv = uvn;
            }
            sv = snv;
        }
    }
}

// ---------------- launch ----------------
extern "C" void kernel_launch(void* const* d_in, const int* in_sizes, int n_in,
                              void* d_out, int out_size) {
    const float* states = (const float*)d_in[0];   // (64,128,1024)
    const float* mr     = (const float*)d_in[1];   // (64,512,1024)
    const float* memin  = (const float*)d_in[2];   // (2048,1024)
    const float* index  = (const float*)d_in[3];   // (2048,1)
    float* out = (float*)d_out;                    // targets(64*1024) ++ importances(64)

    k_reset<<<1, 128>>>();
    mega<<<NB, NT>>>(states, mr, memin, index, out);
}